// round 12
// baseline (speedup 1.0000x reference)
#include <cuda_runtime.h>
#include <cuda_bf16.h>
#include <cuda_fp16.h>
#include <math.h>
#include <stdint.h>

// ---------------- problem constants ----------------
#define B      16
#define CIN    15          // C*T = 3*5
#define HIN    384
#define GH     192         // gating conv out spatial
#define PH     96          // pooled / expert spatial
#define NEXP   3
#define N_OUT  (B*6*PH*PH)   // 884736

// ---------------- device scratch ----------------
__device__ float g_gate[B*64*GH*GH];
__device__ float g_feat[B*64];
__device__ int   g_idx[B];
__device__ float g_y1[B*64*PH*PH];              // [b][ic][96][96]
__device__ float g_y2[B*384*PH*PH];             // [b][oc][px]
__device__ __nv_bfloat16 g_wh[NEXP*9*384*64];   // head w1 hi [e][tap][oc][ic]
__device__ __nv_bfloat16 g_wl[NEXP*9*384*64];   // lo
__device__ __half        g_gwf[49*64*16];       // gating w fp16 [tap][oc][ic16]
__device__ __nv_bfloat16 g_ewh[NEXP*49*64*16];  // expert conv1 w hi [e][tap][oc][ic16]
__device__ __nv_bfloat16 g_ewl[NEXP*49*64*16];
__device__ __nv_bfloat16 g_y1th[B*PH*PH*64];    // y1 split hi, [b][px][ic]
__device__ __nv_bfloat16 g_y1tl[B*PH*PH*64];    // lo

// ---------------- helpers ----------------
__device__ __forceinline__ uint32_t smem_u32(const void* p) {
    uint32_t a;
    asm("{ .reg .u64 t; cvta.to.shared.u64 t, %1; cvt.u32.u64 %0, t; }" : "=r"(a) : "l"(p));
    return a;
}
#define SW128(x) ((x) ^ (((x) >> 3) & 0x70))

__device__ __forceinline__ uint32_t pkbf(__nv_bfloat16 a, __nv_bfloat16 b) {
    __nv_bfloat162 t = __halves2bfloat162(a, b);
    return *reinterpret_cast<uint32_t*>(&t);
}
__device__ __forceinline__ uint32_t pkhf(float a, float b) {
    __half2 t = __floats2half2_rn(a, b);
    return *reinterpret_cast<uint32_t*>(&t);
}

#define LDSM4(r0, r1, r2, r3, a) \
    asm volatile("ldmatrix.sync.aligned.m8n8.x4.shared.b16 {%0,%1,%2,%3}, [%4];" \
        : "=r"(r0), "=r"(r1), "=r"(r2), "=r"(r3) : "r"(a))

#define MMA16816(d, a, b0, b1) \
    asm volatile("mma.sync.aligned.m16n8k16.row.col.f32.bf16.bf16.f32 " \
        "{%0,%1,%2,%3}, {%4,%5,%6,%7}, {%8,%9}, {%0,%1,%2,%3};" \
        : "+f"((d)[0]), "+f"((d)[1]), "+f"((d)[2]), "+f"((d)[3]) \
        : "r"((a)[0]), "r"((a)[1]), "r"((a)[2]), "r"((a)[3]), "r"(b0), "r"(b1))

#define MMA16816F(d, a, b0, b1) \
    asm volatile("mma.sync.aligned.m16n8k16.row.col.f32.f16.f16.f32 " \
        "{%0,%1,%2,%3}, {%4,%5,%6,%7}, {%8,%9}, {%0,%1,%2,%3};" \
        : "+f"((d)[0]), "+f"((d)[1]), "+f"((d)[2]), "+f"((d)[3]) \
        : "r"((a)[0]), "r"((a)[1]), "r"((a)[2]), "r"((a)[3]), "r"(b0), "r"(b1))

// stage-area byte offsets, 48B rows (conflict-free)
#define GSA    0
#define GSB    3072
#define SA_HI 0
#define SA_LO 3072
#define SB_HI 6144
#define SB_LO 18432

// =====================================================================
// weight convert kernels
// =====================================================================
__global__ void gw_convert(const float* __restrict__ w)   // [64][15][7][7] -> fp16
{
    int i = blockIdx.x * 256 + threadIdx.x;
    if (i >= 49*64*16) return;
    int ic = i & 15, oc = (i >> 4) & 63, tap = i >> 10;
    float v = (ic < 15) ? w[oc*735 + ic*49 + tap] : 0.f;
    g_gwf[i] = __float2half_rn(v);
}

__global__ void ew_convert(const float* __restrict__ w)   // [E][64][15][7][7]
{
    int i = blockIdx.x * 256 + threadIdx.x;
    if (i >= NEXP*49*64*16) return;
    int ic = i & 15, oc = (i >> 4) & 63, tap = (i >> 10) % 49, e = i / (49*1024);
    float v = (ic < 15) ? w[((e*64 + oc)*15 + ic)*49 + tap] : 0.f;
    __nv_bfloat16 h = __float2bfloat16_rn(v);
    __nv_bfloat16 l = __float2bfloat16_rn(v - __bfloat162float(h));
    g_ewh[i] = h;
    g_ewl[i] = l;
}

__global__ void w_convert(const float* __restrict__ w)    // head w1 [E][384][64][3][3]
{
    int i = blockIdx.x * 256 + threadIdx.x;
    if (i >= NEXP*384*64*9) return;
    int tap = i % 9;
    int r   = i / 9;
    int ic  = r % 64;
    int r2  = r / 64;
    int oc  = r2 % 384;
    int e   = r2 / 384;
    float v = w[i];
    __nv_bfloat16 h = __float2bfloat16_rn(v);
    __nv_bfloat16 l = __float2bfloat16_rn(v - __bfloat162float(h));
    int dst = ((e*9 + tap)*384 + oc)*64 + ic;
    g_wh[dst] = h;
    g_wl[dst] = l;
}

// =====================================================================
// y1 split: [b][ic][96][96] fp32 -> [b][px][64] bf16 hi/lo (once)
// =====================================================================
__global__ void y1_convert()
{
    __shared__ float s[64*65];
    const int b   = blockIdx.y;
    const int px0 = blockIdx.x * 64;
    const int tid = threadIdx.x;
    #pragma unroll
    for (int k = 0; k < 16; k++) {
        int i  = k*256 + tid;        // 0..4095
        int ic = i >> 6, px = i & 63;
        s[ic*65 + px] = g_y1[((size_t)(b*64 + ic))*(PH*PH) + px0 + px];
    }
    __syncthreads();
    const int px = tid >> 2, part = tid & 3;
    uint32_t hp[8], lq[8];
    #pragma unroll
    for (int u = 0; u < 16; u += 2) {
        int ic = part*16 + u;
        float v0 = s[ic*65 + px];
        float v1 = s[(ic+1)*65 + px];
        __nv_bfloat16 h0 = __float2bfloat16_rn(v0);
        __nv_bfloat16 h1 = __float2bfloat16_rn(v1);
        hp[u >> 1] = pkbf(h0, h1);
        __nv_bfloat16 l0 = __float2bfloat16_rn(v0 - __bfloat162float(h0));
        __nv_bfloat16 l1 = __float2bfloat16_rn(v1 - __bfloat162float(h1));
        lq[u >> 1] = pkbf(l0, l1);
    }
    const size_t rec = ((size_t)b*(PH*PH) + px0 + px)*64 + part*16;
    *(uint4*)(g_y1th + rec)     = make_uint4(hp[0], hp[1], hp[2], hp[3]);
    *(uint4*)(g_y1th + rec + 8) = make_uint4(hp[4], hp[5], hp[6], hp[7]);
    *(uint4*)(g_y1tl + rec)     = make_uint4(lq[0], lq[1], lq[2], lq[3]);
    *(uint4*)(g_y1tl + rec + 8) = make_uint4(lq[4], lq[5], lq[6], lq[7]);
}

// =====================================================================
// Kernel 1: gating conv 7x7 s2 p3 (15->64) + BN + ReLU, fp16 single (R11 verified)
// =====================================================================
__global__ void __launch_bounds__(256)
gating_mma(const float* __restrict__ x,
           const float* __restrict__ gamma,
           const float* __restrict__ beta,
           const float* __restrict__ mean,
           const float* __restrict__ var)
{
    extern __shared__ char smem[];
    const uint32_t sb = smem_u32(smem);
    const int tid = threadIdx.x;
    const int wid = tid >> 5, lid = tid & 31;
    const int b   = blockIdx.y;
    const int p0  = blockIdx.x * 256;
    const int n0w = wid * 32;

    float acc[4][4][4];
    #pragma unroll
    for (int mt = 0; mt < 4; mt++)
        #pragma unroll
        for (int nt = 0; nt < 4; nt++)
            #pragma unroll
            for (int q = 0; q < 4; q++) acc[mt][nt][q] = 0.f;

    const int p  = p0 + tid;
    const int oh = p / GH, ow = p - oh*GH;
    const int ih0 = oh*2 - 3, iw0 = ow*2 - 3;
    const float* xb = x + (size_t)b * CIN * HIN * HIN;

    const int rr = lid & 7, sel = lid >> 3;
    const int arow = tid >> 2, apart = tid & 3;

    for (int tap = 0; tap < 49; tap++) {
        const int kh = tap / 7, kw = tap - 7*(tap/7);
        __syncthreads();

        *(uint2*)(smem + GSA + arow*48 + apart*8) =
            *(const uint2*)(g_gwf + tap*1024 + arow*16 + apart*4);

        {
            const int ih = ih0 + kh, iw = iw0 + kw;
            const bool ok = ((unsigned)ih < (unsigned)HIN) && ((unsigned)iw < (unsigned)HIN);
            const float* xq = xb + (size_t)ih*HIN + iw;
            uint32_t hp[8];
            #pragma unroll
            for (int u = 0; u < 16; u += 2) {
                float v0 = (u < 15 && ok)     ? __ldg(xq + (size_t)u     * (HIN*HIN)) : 0.f;
                float v1 = (u + 1 < 15 && ok) ? __ldg(xq + (size_t)(u+1) * (HIN*HIN)) : 0.f;
                hp[u >> 1] = pkhf(v0, v1);
            }
            *(uint4*)(smem + GSB + tid*48)      = make_uint4(hp[0], hp[1], hp[2], hp[3]);
            *(uint4*)(smem + GSB + tid*48 + 16) = make_uint4(hp[4], hp[5], hp[6], hp[7]);
        }
        __syncthreads();

        uint32_t ah[4][4];
        #pragma unroll
        for (int mt = 0; mt < 4; mt++) {
            const uint32_t offA = (mt*16 + (sel & 1)*8 + rr)*48 + (sel >> 1)*16;
            LDSM4(ah[mt][0], ah[mt][1], ah[mt][2], ah[mt][3], sb + GSA + offA);
        }
        uint32_t bh[4][2];
        #pragma unroll
        for (int pair = 0; pair < 2; pair++) {
            const uint32_t offB = (n0w + pair*16 + (sel >> 1)*8 + rr)*48 + (sel & 1)*16;
            LDSM4(bh[pair*2][0], bh[pair*2][1], bh[pair*2+1][0], bh[pair*2+1][1],
                  sb + GSB + offB);
        }
        #pragma unroll
        for (int mt = 0; mt < 4; mt++)
            #pragma unroll
            for (int nt = 0; nt < 4; nt++)
                MMA16816F(acc[mt][nt], ah[mt], bh[nt][0], bh[nt][1]);
    }

    __syncthreads();
    float* epi = (float*)smem;
    {
        const int r  = lid >> 2;
        const int cc = (lid & 3) * 2;
        #pragma unroll
        for (int mt = 0; mt < 4; mt++)
            #pragma unroll
            for (int nt = 0; nt < 4; nt++) {
                const int m  = mt*16 + r;
                const int nn = n0w + nt*8 + cc;
                epi[m*256 + nn]         = acc[mt][nt][0];
                epi[m*256 + nn + 1]     = acc[mt][nt][1];
                epi[(m+8)*256 + nn]     = acc[mt][nt][2];
                epi[(m+8)*256 + nn + 1] = acc[mt][nt][3];
            }
    }
    __syncthreads();
    #pragma unroll
    for (int it = 0; it < 16; it++) {
        int i  = it*256 + tid;
        int oc = i >> 6;
        int cx = (i & 63) * 4;
        float4 v = *(float4*)&epi[oc*256 + cx];
        float inv = gamma[oc] * rsqrtf(var[oc] + 1e-5f);
        float bia = beta[oc] - mean[oc]*inv;
        v.x = fmaxf(v.x*inv + bia, 0.f);
        v.y = fmaxf(v.y*inv + bia, 0.f);
        v.z = fmaxf(v.z*inv + bia, 0.f);
        v.w = fmaxf(v.w*inv + bia, 0.f);
        *(float4*)&g_gate[((size_t)(b*64 + oc))*(GH*GH) + p0 + cx] = v;
    }
}

// =====================================================================
// Kernel 4: expert conv1 7x7 s4 p3 (15->64) + bias + ReLU, bf16 split (R5 verified)
// =====================================================================
__global__ void __launch_bounds__(256)
expert_mma(const float* __restrict__ x,
           const float* __restrict__ eb)
{
    extern __shared__ char smem[];
    const uint32_t sb = smem_u32(smem);
    const int tid = threadIdx.x;
    const int wid = tid >> 5, lid = tid & 31;
    const int b   = blockIdx.y;
    const int e   = g_idx[b];
    const int p0  = blockIdx.x * 256;
    const int n0w = wid * 32;

    float acc[4][4][4];
    #pragma unroll
    for (int mt = 0; mt < 4; mt++)
        #pragma unroll
        for (int nt = 0; nt < 4; nt++)
            #pragma unroll
            for (int q = 0; q < 4; q++) acc[mt][nt][q] = 0.f;

    const int p  = p0 + tid;
    const int oh = p / PH, ow = p - oh*PH;
    const int ih0 = oh*4 - 3, iw0 = ow*4 - 3;
    const float* xb = x + (size_t)b * CIN * HIN * HIN;

    const int rr = lid & 7, sel = lid >> 3;
    const int arow = tid >> 2, apart = tid & 3;
    const __nv_bfloat16* ewh = g_ewh + (size_t)e * 49*1024;
    const __nv_bfloat16* ewl = g_ewl + (size_t)e * 49*1024;

    for (int tap = 0; tap < 49; tap++) {
        const int kh = tap / 7, kw = tap - 7*(tap/7);
        __syncthreads();

        {
            const __nv_bfloat16* sh = ewh + tap*1024 + arow*16 + apart*4;
            const __nv_bfloat16* sl = ewl + tap*1024 + arow*16 + apart*4;
            *(uint2*)(smem + SA_HI + arow*48 + apart*8) = *(const uint2*)sh;
            *(uint2*)(smem + SA_LO + arow*48 + apart*8) = *(const uint2*)sl;
        }
        {
            const int ih = ih0 + kh, iw = iw0 + kw;
            const bool ok = ((unsigned)ih < (unsigned)HIN) && ((unsigned)iw < (unsigned)HIN);
            const float* xq = xb + (size_t)ih*HIN + iw;
            uint32_t hp[8], lp[8];
            #pragma unroll
            for (int u = 0; u < 16; u += 2) {
                float v0 = (u < 15 && ok)     ? __ldg(xq + (size_t)u     * (HIN*HIN)) : 0.f;
                float v1 = (u + 1 < 15 && ok) ? __ldg(xq + (size_t)(u+1) * (HIN*HIN)) : 0.f;
                __nv_bfloat16 h0 = __float2bfloat16_rn(v0);
                __nv_bfloat16 h1 = __float2bfloat16_rn(v1);
                hp[u >> 1] = pkbf(h0, h1);
                __nv_bfloat16 l0 = __float2bfloat16_rn(v0 - __bfloat162float(h0));
                __nv_bfloat16 l1 = __float2bfloat16_rn(v1 - __bfloat162float(h1));
                lp[u >> 1] = pkbf(l0, l1);
            }
            *(uint4*)(smem + SB_HI + tid*48)      = make_uint4(hp[0], hp[1], hp[2], hp[3]);
            *(uint4*)(smem + SB_HI + tid*48 + 16) = make_uint4(hp[4], hp[5], hp[6], hp[7]);
            *(uint4*)(smem + SB_LO + tid*48)      = make_uint4(lp[0], lp[1], lp[2], lp[3]);
            *(uint4*)(smem + SB_LO + tid*48 + 16) = make_uint4(lp[4], lp[5], lp[6], lp[7]);
        }
        __syncthreads();

        uint32_t ah[4][4], al[4][4];
        #pragma unroll
        for (int mt = 0; mt < 4; mt++) {
            const uint32_t offA = (mt*16 + (sel & 1)*8 + rr)*48 + (sel >> 1)*16;
            LDSM4(ah[mt][0], ah[mt][1], ah[mt][2], ah[mt][3], sb + SA_HI + offA);
            LDSM4(al[mt][0], al[mt][1], al[mt][2], al[mt][3], sb + SA_LO + offA);
        }
        uint32_t bh[4][2], bl[4][2];
        #pragma unroll
        for (int pair = 0; pair < 2; pair++) {
            const uint32_t offB = (n0w + pair*16 + (sel >> 1)*8 + rr)*48 + (sel & 1)*16;
            LDSM4(bh[pair*2][0], bh[pair*2][1], bh[pair*2+1][0], bh[pair*2+1][1],
                  sb + SB_HI + offB);
            LDSM4(bl[pair*2][0], bl[pair*2][1], bl[pair*2+1][0], bl[pair*2+1][1],
                  sb + SB_LO + offB);
        }
        #pragma unroll
        for (int mt = 0; mt < 4; mt++)
            #pragma unroll
            for (int nt = 0; nt < 4; nt++) {
                MMA16816(acc[mt][nt], ah[mt], bh[nt][0], bh[nt][1]);
                MMA16816(acc[mt][nt], ah[mt], bl[nt][0], bl[nt][1]);
                MMA16816(acc[mt][nt], al[mt], bh[nt][0], bh[nt][1]);
            }
    }

    __syncthreads();
    float* epi = (float*)smem;
    {
        const int r  = lid >> 2;
        const int cc = (lid & 3) * 2;
        #pragma unroll
        for (int mt = 0; mt < 4; mt++)
            #pragma unroll
            for (int nt = 0; nt < 4; nt++) {
                const int m  = mt*16 + r;
                const int nn = n0w + nt*8 + cc;
                epi[m*256 + nn]         = acc[mt][nt][0];
                epi[m*256 + nn + 1]     = acc[mt][nt][1];
                epi[(m+8)*256 + nn]     = acc[mt][nt][2];
                epi[(m+8)*256 + nn + 1] = acc[mt][nt][3];
            }
    }
    __syncthreads();
    const float* bb = eb + e*64;
    #pragma unroll
    for (int it = 0; it < 16; it++) {
        int i  = it*256 + tid;
        int oc = i >> 6;
        int cx = (i & 63) * 4;
        float4 v = *(float4*)&epi[oc*256 + cx];
        float bias = bb[oc];
        v.x = fmaxf(v.x + bias, 0.f);
        v.y = fmaxf(v.y + bias, 0.f);
        v.z = fmaxf(v.z + bias, 0.f);
        v.w = fmaxf(v.w + bias, 0.f);
        *(float4*)&g_y1[((size_t)(b*64 + oc))*(PH*PH) + p0 + cx] = v;
    }
}

// =====================================================================
// Kernel 2: maxpool 3x3 s2 p1 + spatial mean
// =====================================================================
__global__ void pool_mean()
{
    const int bc = blockIdx.x;
    const float* src = g_gate + (size_t)bc * GH * GH;
    const int tid = threadIdx.x;
    float sum = 0.f;
    for (int p = tid; p < PH*PH; p += 256) {
        int ph = p / PH, pw = p - ph*PH;
        float m = -1e30f;
        #pragma unroll
        for (int r = 0; r < 3; r++) {
            int ih = 2*ph - 1 + r;
            if ((unsigned)ih >= (unsigned)GH) continue;
            #pragma unroll
            for (int c = 0; c < 3; c++) {
                int iw = 2*pw - 1 + c;
                if ((unsigned)iw >= (unsigned)GH) continue;
                m = fmaxf(m, src[ih*GH + iw]);
            }
        }
        sum += m;
    }
    __shared__ float red[256];
    red[tid] = sum;
    __syncthreads();
    for (int s = 128; s > 0; s >>= 1) {
        if (tid < s) red[tid] += red[tid + s];
        __syncthreads();
    }
    if (tid == 0) g_feat[bc] = red[0] / (float)(PH*PH);
}

// =====================================================================
// Kernel 3: logits, argmax, aux loss
// =====================================================================
__global__ void gate_head(const float* __restrict__ fcw,
                          const float* __restrict__ fcb,
                          float* __restrict__ out, int out_size)
{
    __shared__ float lg[B][NEXP];
    __shared__ float proxy[NEXP];
    __shared__ int   cnt[NEXP];
    const int t = threadIdx.x;

    if (t < NEXP) { proxy[t] = 0.f; cnt[t] = 0; }
    if (t < B*NEXP) {
        int b = t / NEXP, e = t - b*NEXP;
        float s = fcb[e];
        const float* f = g_feat + b*64;
        const float* wr = fcw + e*64;
        for (int c = 0; c < 64; c++) s += f[c]*wr[c];
        lg[b][e] = s;
    }
    __syncthreads();
    if (t < B) {
        float l0 = lg[t][0], l1 = lg[t][1], l2 = lg[t][2];
        int am = 0; float bm = l0;
        if (l1 > bm) { bm = l1; am = 1; }
        if (l2 > bm) { bm = l2; am = 2; }
        g_idx[t] = am;
        atomicAdd(&cnt[am], 1);
        float m = bm;
        float e0 = expf(l0 - m), e1 = expf(l1 - m), e2 = expf(l2 - m);
        float s = e0 + e1 + e2;
        atomicAdd(&proxy[0], e0/s);
        atomicAdd(&proxy[1], e1/s);
        atomicAdd(&proxy[2], e2/s);
    }
    __syncthreads();
    if (t == 0 && out_size > N_OUT) {
        float aux = 0.f;
        for (int e = 0; e < NEXP; e++)
            aux += ((float)cnt[e] / (float)B) * (proxy[e] / (float)B);
        out[N_OUT] = 0.01f * (aux * (float)NEXP);
    }
}

// =====================================================================
// Kernel 5: head conv1 3x3 s1 p1 (64->384), bf16 split MMA
// B-build now vectorized loads from pre-split g_y1th/g_y1tl
// =====================================================================
__global__ void __launch_bounds__(256)
head_conv1_mma(const float* __restrict__ hb1)
{
    extern __shared__ char smem[];
    const uint32_t sb = smem_u32(smem);
    const int tid = threadIdx.x;
    const int wid = tid >> 5, lid = tid & 31;
    const int b   = blockIdx.z;
    const int ocb = blockIdx.y;
    const int p0  = blockIdx.x * 128;
    const int e   = g_idx[b];

    const int warpM = wid >> 2, warpN = wid & 3;
    const int m0w = warpM * 64, n0w = warpN * 32;

    float acc[4][4][4];
    #pragma unroll
    for (int mt = 0; mt < 4; mt++)
        #pragma unroll
        for (int nt = 0; nt < 4; nt++)
            #pragma unroll
            for (int q = 0; q < 4; q++) acc[mt][nt][q] = 0.f;

    const int n = tid & 127;
    const int g = tid >> 7;
    const int p = p0 + n;
    const int pr = p / 96;
    const int pc = p - pr*96;
    const __nv_bfloat16* yth = g_y1th + (size_t)b * (PH*PH) * 64;
    const __nv_bfloat16* ytl = g_y1tl + (size_t)b * (PH*PH) * 64;

    const int rr  = lid & 7;
    const int sel = lid >> 3;
    const uint4 z4 = make_uint4(0,0,0,0);

    for (int tap = 0; tap < 9; tap++) {
        const int kh = tap / 3, kw = tap - 3*(tap/3);
        __syncthreads();

        {
            const __nv_bfloat16* whb = g_wh + ((size_t)((e*9 + tap)*384 + ocb*128))*64;
            const __nv_bfloat16* wlb = g_wl + ((size_t)((e*9 + tap)*384 + ocb*128))*64;
            #pragma unroll
            for (int it = 0; it < 8; it++) {
                int idx = it*256 + tid;
                int s   = idx >> 10;
                int r   = idx & 1023;
                int oc  = r >> 3;
                int ch  = r & 7;
                const __nv_bfloat16* src = (s ? wlb : whb) + oc*64 + ch*8;
                uint4 v = *(const uint4*)src;
                *(uint4*)(smem + s*16384 + SW128((uint32_t)(oc*128 + ch*16))) = v;
            }
        }

        {
            const int ri = pr + kh - 1, ci = pc + kw - 1;
            const bool ok = ((unsigned)ri < 96u) && ((unsigned)ci < 96u);
            const size_t rec = ((size_t)(ri*96 + ci))*64 + g*32;
            const uint4* ph = (const uint4*)(yth + rec);
            const uint4* pl = (const uint4*)(ytl + rec);
            #pragma unroll
            for (int j = 0; j < 4; j++) {
                uint4 vh = ok ? ph[j] : z4;
                uint4 vl = ok ? pl[j] : z4;
                const uint32_t off = SW128((uint32_t)(n*128 + g*64 + j*16));
                *(uint4*)(smem + 32768 + off) = vh;
                *(uint4*)(smem + 49152 + off) = vl;
            }
        }
        __syncthreads();

        #pragma unroll
        for (int kc = 0; kc < 4; kc++) {
            const int k0b = kc*32;

            uint32_t ah[4][4], al[4][4];
            {
                const int arow = m0w + (sel & 1)*8 + rr;
                const int akb  = k0b + ((sel >> 1)*8)*2;
                #pragma unroll
                for (int mt = 0; mt < 4; mt++) {
                    uint32_t off = SW128((uint32_t)((arow + mt*16)*128 + akb));
                    LDSM4(ah[mt][0], ah[mt][1], ah[mt][2], ah[mt][3], sb + off);
                    LDSM4(al[mt][0], al[mt][1], al[mt][2], al[mt][3], sb + 16384 + off);
                }
            }

            uint32_t bh[4][2], bl[4][2];
            {
                const int brow = n0w + (sel >> 1)*8 + rr;
                const int bkb  = k0b + ((sel & 1)*8)*2;
                #pragma unroll
                for (int pair = 0; pair < 2; pair++) {
                    uint32_t off = SW128((uint32_t)((brow + pair*16)*128 + bkb));
                    LDSM4(bh[pair*2][0], bh[pair*2][1], bh[pair*2+1][0], bh[pair*2+1][1],
                          sb + 32768 + off);
                    LDSM4(bl[pair*2][0], bl[pair*2][1], bl[pair*2+1][0], bl[pair*2+1][1],
                          sb + 49152 + off);
                }
            }

            #pragma unroll
            for (int mt = 0; mt < 4; mt++)
                #pragma unroll
                for (int nt = 0; nt < 4; nt++) {
                    MMA16816(acc[mt][nt], ah[mt], bh[nt][0], bh[nt][1]);
                    MMA16816(acc[mt][nt], ah[mt], bl[nt][0], bl[nt][1]);
                    MMA16816(acc[mt][nt], al[mt], bh[nt][0], bh[nt][1]);
                }
        }
    }

    __syncthreads();
    float* epi = (float*)smem;
    {
        const int r  = lid >> 2;
        const int cc = (lid & 3) * 2;
        #pragma unroll
        for (int mt = 0; mt < 4; mt++)
            #pragma unroll
            for (int nt = 0; nt < 4; nt++) {
                const int m  = m0w + mt*16 + r;
                const int nn = n0w + nt*8 + cc;
                epi[m*128 + nn]         = acc[mt][nt][0];
                epi[m*128 + nn + 1]     = acc[mt][nt][1];
                epi[(m+8)*128 + nn]     = acc[mt][nt][2];
                epi[(m+8)*128 + nn + 1] = acc[mt][nt][3];
            }
    }
    __syncthreads();
    {
        const float* bb = hb1 + e*384 + ocb*128;
        #pragma unroll
        for (int it = 0; it < 16; it++) {
            int i  = it*256 + tid;
            int oc = i >> 5;
            int cx = (i & 31) * 4;
            float4 v = *(float4*)&epi[oc*128 + cx];
            float bias = bb[oc];
            v.x = fmaxf(v.x + bias, 0.f);
            v.y = fmaxf(v.y + bias, 0.f);
            v.z = fmaxf(v.z + bias, 0.f);
            v.w = fmaxf(v.w + bias, 0.f);
            *(float4*)&g_y2[((size_t)(b*384 + ocb*128 + oc))*(PH*PH) + p0 + cx] = v;
        }
    }
}

// =====================================================================
// Kernel 6: grouped 1x1 conv (384 -> 6, groups=3) + bias
// =====================================================================
__global__ void head_conv2(const float* __restrict__ hw2,
                           const float* __restrict__ hb2,
                           float* __restrict__ out)
{
    const int b = blockIdx.z;
    const int g = blockIdx.y;
    const int e = g_idx[b];
    const int tid = threadIdx.x;
    const int p = blockIdx.x * 256 + tid;

    __shared__ float w0s[128], w1s[128];
    if (tid < 128) {
        w0s[tid] = hw2[(e*6 + 2*g)    *128 + tid];
        w1s[tid] = hw2[(e*6 + 2*g + 1)*128 + tid];
    }
    __syncthreads();

    float a0 = hb2[e*6 + 2*g];
    float a1 = hb2[e*6 + 2*g + 1];
    const float* yp = g_y2 + ((size_t)b*384 + g*128) * (PH*PH) + p;
    #pragma unroll 8
    for (int ic = 0; ic < 128; ic++) {
        float v = yp[(size_t)ic * (PH*PH)];
        a0 += v * w0s[ic];
        a1 += v * w1s[ic];
    }
    out[((size_t)b*6 + 2*g)    *(PH*PH) + p] = a0;
    out[((size_t)b*6 + 2*g + 1)*(PH*PH) + p] = a1;
}

// =====================================================================
// launcher
// =====================================================================
extern "C" void kernel_launch(void* const* d_in, const int* in_sizes, int n_in,
                              void* d_out, int out_size)
{
    const float* x        = (const float*)d_in[0];
    const float* g_conv_w = (const float*)d_in[1];
    const float* g_gamma  = (const float*)d_in[2];
    const float* g_beta   = (const float*)d_in[3];
    const float* g_mean   = (const float*)d_in[4];
    const float* g_var    = (const float*)d_in[5];
    const float* g_fc_w   = (const float*)d_in[6];
    const float* g_fc_b   = (const float*)d_in[7];
    const float* e_conv1_w = (const float*)d_in[8];
    const float* e_conv1_b = (const float*)d_in[9];
    const float* e_head_w1 = (const float*)d_in[10];
    const float* e_head_b1 = (const float*)d_in[11];
    const float* e_head_w2 = (const float*)d_in[12];
    const float* e_head_b2 = (const float*)d_in[13];
    float* out = (float*)d_out;

    cudaFuncSetAttribute(head_conv1_mma,
                         cudaFuncAttributeMaxDynamicSharedMemorySize, 65536);
    cudaFuncSetAttribute(gating_mma,
                         cudaFuncAttributeMaxDynamicSharedMemorySize, 65536);
    cudaFuncSetAttribute(expert_mma,
                         cudaFuncAttributeMaxDynamicSharedMemorySize, 65536);

    gw_convert<<<(49*64*16 + 255)/256, 256>>>(g_conv_w);
    ew_convert<<<(NEXP*49*64*16 + 255)/256, 256>>>(e_conv1_w);
    w_convert<<<(NEXP*384*64*9 + 255)/256, 256>>>(e_head_w1);

    dim3 ggate(GH*GH/256, B);                    // 144, 16
    gating_mma<<<ggate, 256, 65536>>>(x, g_gamma, g_beta, g_mean, g_var);

    pool_mean<<<B*64, 256>>>();

    gate_head<<<1, 64>>>(g_fc_w, g_fc_b, out, out_size);

    dim3 gexp(PH*PH/256, B);                     // 36, 16
    expert_mma<<<gexp, 256, 65536>>>(x, e_conv1_b);

    dim3 gy1(PH*PH/64, B);                       // 144, 16
    y1_convert<<<gy1, 256>>>();

    dim3 ghead(PH*PH/128, 3, B);                 // 72, 3, 16
    head_conv1_mma<<<ghead, 256, 65536>>>(e_head_b1);

    dim3 gh2(PH*PH/256, 3, B);                   // 36, 3, 16
    head_conv2<<<gh2, 256>>>(e_head_w2, e_head_b2, out);
}

// round 13
// speedup vs baseline: 1.1619x; 1.1619x over previous
#include <cuda_runtime.h>
#include <cuda_bf16.h>
#include <cuda_fp16.h>
#include <math.h>
#include <stdint.h>

// ---------------- problem constants ----------------
#define B      16
#define CIN    15          // C*T = 3*5
#define HIN    384
#define GH     192         // gating conv out spatial
#define PH     96          // pooled / expert spatial
#define NEXP   3
#define N_OUT  (B*6*PH*PH)   // 884736

// ---------------- device scratch ----------------
__device__ float g_gate[B*64*GH*GH];
__device__ float g_feat[B*64];
__device__ int   g_idx[B];
__device__ uint32_t g_y1p[B*64*PH*PH];          // y1 packed (bf16 lo<<16 | hi), [b][ic][96][96]
__device__ float g_y2[B*384*PH*PH];             // [b][oc][px]
__device__ __nv_bfloat16 g_wh[NEXP*9*384*64];   // head w1 hi [e][tap][oc][ic]
__device__ __nv_bfloat16 g_wl[NEXP*9*384*64];   // lo
__device__ __half        g_gwf[49*64*16];       // gating w fp16 [tap][oc][ic16]
__device__ __nv_bfloat16 g_ewh[NEXP*49*64*16];  // expert conv1 w hi [e][tap][oc][ic16]
__device__ __nv_bfloat16 g_ewl[NEXP*49*64*16];

// ---------------- helpers ----------------
__device__ __forceinline__ uint32_t smem_u32(const void* p) {
    uint32_t a;
    asm("{ .reg .u64 t; cvta.to.shared.u64 t, %1; cvt.u32.u64 %0, t; }" : "=r"(a) : "l"(p));
    return a;
}
#define SW128(x) ((x) ^ (((x) >> 3) & 0x70))

__device__ __forceinline__ uint32_t pkbf(__nv_bfloat16 a, __nv_bfloat16 b) {
    __nv_bfloat162 t = __halves2bfloat162(a, b);
    return *reinterpret_cast<uint32_t*>(&t);
}
__device__ __forceinline__ uint32_t pkhf(float a, float b) {
    __half2 t = __floats2half2_rn(a, b);
    return *reinterpret_cast<uint32_t*>(&t);
}
// pack one fp32 value into (bf16_lo << 16) | bf16_hi
__device__ __forceinline__ uint32_t pack_split(float v) {
    __nv_bfloat16 h = __float2bfloat16_rn(v);
    __nv_bfloat16 l = __float2bfloat16_rn(v - __bfloat162float(h));
    return pkbf(h, l);
}

#define LDSM4(r0, r1, r2, r3, a) \
    asm volatile("ldmatrix.sync.aligned.m8n8.x4.shared.b16 {%0,%1,%2,%3}, [%4];" \
        : "=r"(r0), "=r"(r1), "=r"(r2), "=r"(r3) : "r"(a))

#define MMA16816(d, a, b0, b1) \
    asm volatile("mma.sync.aligned.m16n8k16.row.col.f32.bf16.bf16.f32 " \
        "{%0,%1,%2,%3}, {%4,%5,%6,%7}, {%8,%9}, {%0,%1,%2,%3};" \
        : "+f"((d)[0]), "+f"((d)[1]), "+f"((d)[2]), "+f"((d)[3]) \
        : "r"((a)[0]), "r"((a)[1]), "r"((a)[2]), "r"((a)[3]), "r"(b0), "r"(b1))

#define MMA16816F(d, a, b0, b1) \
    asm volatile("mma.sync.aligned.m16n8k16.row.col.f32.f16.f16.f32 " \
        "{%0,%1,%2,%3}, {%4,%5,%6,%7}, {%8,%9}, {%0,%1,%2,%3};" \
        : "+f"((d)[0]), "+f"((d)[1]), "+f"((d)[2]), "+f"((d)[3]) \
        : "r"((a)[0]), "r"((a)[1]), "r"((a)[2]), "r"((a)[3]), "r"(b0), "r"(b1))

// stage-area byte offsets, 48B rows (conflict-free)
#define GSA    0
#define GSB    3072
#define SA_HI 0
#define SA_LO 3072
#define SB_HI 6144
#define SB_LO 18432

// =====================================================================
// weight convert kernels
// =====================================================================
__global__ void gw_convert(const float* __restrict__ w)   // [64][15][7][7] -> fp16
{
    int i = blockIdx.x * 256 + threadIdx.x;
    if (i >= 49*64*16) return;
    int ic = i & 15, oc = (i >> 4) & 63, tap = i >> 10;
    float v = (ic < 15) ? w[oc*735 + ic*49 + tap] : 0.f;
    g_gwf[i] = __float2half_rn(v);
}

__global__ void ew_convert(const float* __restrict__ w)   // [E][64][15][7][7]
{
    int i = blockIdx.x * 256 + threadIdx.x;
    if (i >= NEXP*49*64*16) return;
    int ic = i & 15, oc = (i >> 4) & 63, tap = (i >> 10) % 49, e = i / (49*1024);
    float v = (ic < 15) ? w[((e*64 + oc)*15 + ic)*49 + tap] : 0.f;
    __nv_bfloat16 h = __float2bfloat16_rn(v);
    __nv_bfloat16 l = __float2bfloat16_rn(v - __bfloat162float(h));
    g_ewh[i] = h;
    g_ewl[i] = l;
}

__global__ void w_convert(const float* __restrict__ w)    // head w1 [E][384][64][3][3]
{
    int i = blockIdx.x * 256 + threadIdx.x;
    if (i >= NEXP*384*64*9) return;
    int tap = i % 9;
    int r   = i / 9;
    int ic  = r % 64;
    int r2  = r / 64;
    int oc  = r2 % 384;
    int e   = r2 / 384;
    float v = w[i];
    __nv_bfloat16 h = __float2bfloat16_rn(v);
    __nv_bfloat16 l = __float2bfloat16_rn(v - __bfloat162float(h));
    int dst = ((e*9 + tap)*384 + oc)*64 + ic;
    g_wh[dst] = h;
    g_wl[dst] = l;
}

// =====================================================================
// Kernel 1: gating conv 7x7 s2 p3 (15->64) + BN + ReLU, fp16 single (R11 verified)
// =====================================================================
__global__ void __launch_bounds__(256)
gating_mma(const float* __restrict__ x,
           const float* __restrict__ gamma,
           const float* __restrict__ beta,
           const float* __restrict__ mean,
           const float* __restrict__ var)
{
    extern __shared__ char smem[];
    const uint32_t sb = smem_u32(smem);
    const int tid = threadIdx.x;
    const int wid = tid >> 5, lid = tid & 31;
    const int b   = blockIdx.y;
    const int p0  = blockIdx.x * 256;
    const int n0w = wid * 32;

    float acc[4][4][4];
    #pragma unroll
    for (int mt = 0; mt < 4; mt++)
        #pragma unroll
        for (int nt = 0; nt < 4; nt++)
            #pragma unroll
            for (int q = 0; q < 4; q++) acc[mt][nt][q] = 0.f;

    const int p  = p0 + tid;
    const int oh = p / GH, ow = p - oh*GH;
    const int ih0 = oh*2 - 3, iw0 = ow*2 - 3;
    const float* xb = x + (size_t)b * CIN * HIN * HIN;

    const int rr = lid & 7, sel = lid >> 3;
    const int arow = tid >> 2, apart = tid & 3;

    for (int tap = 0; tap < 49; tap++) {
        const int kh = tap / 7, kw = tap - 7*(tap/7);
        __syncthreads();

        *(uint2*)(smem + GSA + arow*48 + apart*8) =
            *(const uint2*)(g_gwf + tap*1024 + arow*16 + apart*4);

        {
            const int ih = ih0 + kh, iw = iw0 + kw;
            const bool ok = ((unsigned)ih < (unsigned)HIN) && ((unsigned)iw < (unsigned)HIN);
            const float* xq = xb + (size_t)ih*HIN + iw;
            uint32_t hp[8];
            #pragma unroll
            for (int u = 0; u < 16; u += 2) {
                float v0 = (u < 15 && ok)     ? __ldg(xq + (size_t)u     * (HIN*HIN)) : 0.f;
                float v1 = (u + 1 < 15 && ok) ? __ldg(xq + (size_t)(u+1) * (HIN*HIN)) : 0.f;
                hp[u >> 1] = pkhf(v0, v1);
            }
            *(uint4*)(smem + GSB + tid*48)      = make_uint4(hp[0], hp[1], hp[2], hp[3]);
            *(uint4*)(smem + GSB + tid*48 + 16) = make_uint4(hp[4], hp[5], hp[6], hp[7]);
        }
        __syncthreads();

        uint32_t ah[4][4];
        #pragma unroll
        for (int mt = 0; mt < 4; mt++) {
            const uint32_t offA = (mt*16 + (sel & 1)*8 + rr)*48 + (sel >> 1)*16;
            LDSM4(ah[mt][0], ah[mt][1], ah[mt][2], ah[mt][3], sb + GSA + offA);
        }
        uint32_t bh[4][2];
        #pragma unroll
        for (int pair = 0; pair < 2; pair++) {
            const uint32_t offB = (n0w + pair*16 + (sel >> 1)*8 + rr)*48 + (sel & 1)*16;
            LDSM4(bh[pair*2][0], bh[pair*2][1], bh[pair*2+1][0], bh[pair*2+1][1],
                  sb + GSB + offB);
        }
        #pragma unroll
        for (int mt = 0; mt < 4; mt++)
            #pragma unroll
            for (int nt = 0; nt < 4; nt++)
                MMA16816F(acc[mt][nt], ah[mt], bh[nt][0], bh[nt][1]);
    }

    __syncthreads();
    float* epi = (float*)smem;
    {
        const int r  = lid >> 2;
        const int cc = (lid & 3) * 2;
        #pragma unroll
        for (int mt = 0; mt < 4; mt++)
            #pragma unroll
            for (int nt = 0; nt < 4; nt++) {
                const int m  = mt*16 + r;
                const int nn = n0w + nt*8 + cc;
                epi[m*256 + nn]         = acc[mt][nt][0];
                epi[m*256 + nn + 1]     = acc[mt][nt][1];
                epi[(m+8)*256 + nn]     = acc[mt][nt][2];
                epi[(m+8)*256 + nn + 1] = acc[mt][nt][3];
            }
    }
    __syncthreads();
    #pragma unroll
    for (int it = 0; it < 16; it++) {
        int i  = it*256 + tid;
        int oc = i >> 6;
        int cx = (i & 63) * 4;
        float4 v = *(float4*)&epi[oc*256 + cx];
        float inv = gamma[oc] * rsqrtf(var[oc] + 1e-5f);
        float bia = beta[oc] - mean[oc]*inv;
        v.x = fmaxf(v.x*inv + bia, 0.f);
        v.y = fmaxf(v.y*inv + bia, 0.f);
        v.z = fmaxf(v.z*inv + bia, 0.f);
        v.w = fmaxf(v.w*inv + bia, 0.f);
        *(float4*)&g_gate[((size_t)(b*64 + oc))*(GH*GH) + p0 + cx] = v;
    }
}

// =====================================================================
// Kernel 4: expert conv1 7x7 s4 p3 (15->64) + bias + ReLU, bf16 split
// (R5/R11 structure; epilogue writes PACKED bf16 hi/lo y1)
// =====================================================================
__global__ void __launch_bounds__(256)
expert_mma(const float* __restrict__ x,
           const float* __restrict__ eb)
{
    extern __shared__ char smem[];
    const uint32_t sb = smem_u32(smem);
    const int tid = threadIdx.x;
    const int wid = tid >> 5, lid = tid & 31;
    const int b   = blockIdx.y;
    const int e   = g_idx[b];
    const int p0  = blockIdx.x * 256;
    const int n0w = wid * 32;

    float acc[4][4][4];
    #pragma unroll
    for (int mt = 0; mt < 4; mt++)
        #pragma unroll
        for (int nt = 0; nt < 4; nt++)
            #pragma unroll
            for (int q = 0; q < 4; q++) acc[mt][nt][q] = 0.f;

    const int p  = p0 + tid;
    const int oh = p / PH, ow = p - oh*PH;
    const int ih0 = oh*4 - 3, iw0 = ow*4 - 3;
    const float* xb = x + (size_t)b * CIN * HIN * HIN;

    const int rr = lid & 7, sel = lid >> 3;
    const int arow = tid >> 2, apart = tid & 3;
    const __nv_bfloat16* ewh = g_ewh + (size_t)e * 49*1024;
    const __nv_bfloat16* ewl = g_ewl + (size_t)e * 49*1024;

    for (int tap = 0; tap < 49; tap++) {
        const int kh = tap / 7, kw = tap - 7*(tap/7);
        __syncthreads();

        {
            const __nv_bfloat16* sh = ewh + tap*1024 + arow*16 + apart*4;
            const __nv_bfloat16* sl = ewl + tap*1024 + arow*16 + apart*4;
            *(uint2*)(smem + SA_HI + arow*48 + apart*8) = *(const uint2*)sh;
            *(uint2*)(smem + SA_LO + arow*48 + apart*8) = *(const uint2*)sl;
        }
        {
            const int ih = ih0 + kh, iw = iw0 + kw;
            const bool ok = ((unsigned)ih < (unsigned)HIN) && ((unsigned)iw < (unsigned)HIN);
            const float* xq = xb + (size_t)ih*HIN + iw;
            uint32_t hp[8], lp[8];
            #pragma unroll
            for (int u = 0; u < 16; u += 2) {
                float v0 = (u < 15 && ok)     ? __ldg(xq + (size_t)u     * (HIN*HIN)) : 0.f;
                float v1 = (u + 1 < 15 && ok) ? __ldg(xq + (size_t)(u+1) * (HIN*HIN)) : 0.f;
                __nv_bfloat16 h0 = __float2bfloat16_rn(v0);
                __nv_bfloat16 h1 = __float2bfloat16_rn(v1);
                hp[u >> 1] = pkbf(h0, h1);
                __nv_bfloat16 l0 = __float2bfloat16_rn(v0 - __bfloat162float(h0));
                __nv_bfloat16 l1 = __float2bfloat16_rn(v1 - __bfloat162float(h1));
                lp[u >> 1] = pkbf(l0, l1);
            }
            *(uint4*)(smem + SB_HI + tid*48)      = make_uint4(hp[0], hp[1], hp[2], hp[3]);
            *(uint4*)(smem + SB_HI + tid*48 + 16) = make_uint4(hp[4], hp[5], hp[6], hp[7]);
            *(uint4*)(smem + SB_LO + tid*48)      = make_uint4(lp[0], lp[1], lp[2], lp[3]);
            *(uint4*)(smem + SB_LO + tid*48 + 16) = make_uint4(lp[4], lp[5], lp[6], lp[7]);
        }
        __syncthreads();

        uint32_t ah[4][4], al[4][4];
        #pragma unroll
        for (int mt = 0; mt < 4; mt++) {
            const uint32_t offA = (mt*16 + (sel & 1)*8 + rr)*48 + (sel >> 1)*16;
            LDSM4(ah[mt][0], ah[mt][1], ah[mt][2], ah[mt][3], sb + SA_HI + offA);
            LDSM4(al[mt][0], al[mt][1], al[mt][2], al[mt][3], sb + SA_LO + offA);
        }
        uint32_t bh[4][2], bl[4][2];
        #pragma unroll
        for (int pair = 0; pair < 2; pair++) {
            const uint32_t offB = (n0w + pair*16 + (sel >> 1)*8 + rr)*48 + (sel & 1)*16;
            LDSM4(bh[pair*2][0], bh[pair*2][1], bh[pair*2+1][0], bh[pair*2+1][1],
                  sb + SB_HI + offB);
            LDSM4(bl[pair*2][0], bl[pair*2][1], bl[pair*2+1][0], bl[pair*2+1][1],
                  sb + SB_LO + offB);
        }
        #pragma unroll
        for (int mt = 0; mt < 4; mt++)
            #pragma unroll
            for (int nt = 0; nt < 4; nt++) {
                MMA16816(acc[mt][nt], ah[mt], bh[nt][0], bh[nt][1]);
                MMA16816(acc[mt][nt], ah[mt], bl[nt][0], bl[nt][1]);
                MMA16816(acc[mt][nt], al[mt], bh[nt][0], bh[nt][1]);
            }
    }

    __syncthreads();
    float* epi = (float*)smem;
    {
        const int r  = lid >> 2;
        const int cc = (lid & 3) * 2;
        #pragma unroll
        for (int mt = 0; mt < 4; mt++)
            #pragma unroll
            for (int nt = 0; nt < 4; nt++) {
                const int m  = mt*16 + r;
                const int nn = n0w + nt*8 + cc;
                epi[m*256 + nn]         = acc[mt][nt][0];
                epi[m*256 + nn + 1]     = acc[mt][nt][1];
                epi[(m+8)*256 + nn]     = acc[mt][nt][2];
                epi[(m+8)*256 + nn + 1] = acc[mt][nt][3];
            }
    }
    __syncthreads();
    const float* bb = eb + e*64;
    #pragma unroll
    for (int it = 0; it < 16; it++) {
        int i  = it*256 + tid;
        int oc = i >> 6;
        int cx = (i & 63) * 4;
        float4 v = *(float4*)&epi[oc*256 + cx];
        float bias = bb[oc];
        v.x = fmaxf(v.x + bias, 0.f);
        v.y = fmaxf(v.y + bias, 0.f);
        v.z = fmaxf(v.z + bias, 0.f);
        v.w = fmaxf(v.w + bias, 0.f);
        uint4 pk;
        pk.x = pack_split(v.x);
        pk.y = pack_split(v.y);
        pk.z = pack_split(v.z);
        pk.w = pack_split(v.w);
        *(uint4*)&g_y1p[((size_t)(b*64 + oc))*(PH*PH) + p0 + cx] = pk;
    }
}

// =====================================================================
// Kernel 2: maxpool 3x3 s2 p1 + spatial mean
// =====================================================================
__global__ void pool_mean()
{
    const int bc = blockIdx.x;
    const float* src = g_gate + (size_t)bc * GH * GH;
    const int tid = threadIdx.x;
    float sum = 0.f;
    for (int p = tid; p < PH*PH; p += 256) {
        int ph = p / PH, pw = p - ph*PH;
        float m = -1e30f;
        #pragma unroll
        for (int r = 0; r < 3; r++) {
            int ih = 2*ph - 1 + r;
            if ((unsigned)ih >= (unsigned)GH) continue;
            #pragma unroll
            for (int c = 0; c < 3; c++) {
                int iw = 2*pw - 1 + c;
                if ((unsigned)iw >= (unsigned)GH) continue;
                m = fmaxf(m, src[ih*GH + iw]);
            }
        }
        sum += m;
    }
    __shared__ float red[256];
    red[tid] = sum;
    __syncthreads();
    for (int s = 128; s > 0; s >>= 1) {
        if (tid < s) red[tid] += red[tid + s];
        __syncthreads();
    }
    if (tid == 0) g_feat[bc] = red[0] / (float)(PH*PH);
}

// =====================================================================
// Kernel 3: logits, argmax, aux loss
// =====================================================================
__global__ void gate_head(const float* __restrict__ fcw,
                          const float* __restrict__ fcb,
                          float* __restrict__ out, int out_size)
{
    __shared__ float lg[B][NEXP];
    __shared__ float proxy[NEXP];
    __shared__ int   cnt[NEXP];
    const int t = threadIdx.x;

    if (t < NEXP) { proxy[t] = 0.f; cnt[t] = 0; }
    if (t < B*NEXP) {
        int b = t / NEXP, e = t - b*NEXP;
        float s = fcb[e];
        const float* f = g_feat + b*64;
        const float* wr = fcw + e*64;
        for (int c = 0; c < 64; c++) s += f[c]*wr[c];
        lg[b][e] = s;
    }
    __syncthreads();
    if (t < B) {
        float l0 = lg[t][0], l1 = lg[t][1], l2 = lg[t][2];
        int am = 0; float bm = l0;
        if (l1 > bm) { bm = l1; am = 1; }
        if (l2 > bm) { bm = l2; am = 2; }
        g_idx[t] = am;
        atomicAdd(&cnt[am], 1);
        float m = bm;
        float e0 = expf(l0 - m), e1 = expf(l1 - m), e2 = expf(l2 - m);
        float s = e0 + e1 + e2;
        atomicAdd(&proxy[0], e0/s);
        atomicAdd(&proxy[1], e1/s);
        atomicAdd(&proxy[2], e2/s);
    }
    __syncthreads();
    if (t == 0 && out_size > N_OUT) {
        float aux = 0.f;
        for (int e = 0; e < NEXP; e++)
            aux += ((float)cnt[e] / (float)B) * (proxy[e] / (float)B);
        out[N_OUT] = 0.01f * (aux * (float)NEXP);
    }
}

// =====================================================================
// Kernel 5: head conv1 3x3 s1 p1 (64->384), bf16 split MMA
// B-build: same plane-major gather as R11, but loads PACKED y1 (byte_perm split)
// =====================================================================
__global__ void __launch_bounds__(256)
head_conv1_mma(const float* __restrict__ hb1)
{
    extern __shared__ char smem[];
    const uint32_t sb = smem_u32(smem);
    const int tid = threadIdx.x;
    const int wid = tid >> 5, lid = tid & 31;
    const int b   = blockIdx.z;
    const int ocb = blockIdx.y;
    const int p0  = blockIdx.x * 128;
    const int e   = g_idx[b];

    const int warpM = wid >> 2, warpN = wid & 3;
    const int m0w = warpM * 64, n0w = warpN * 32;

    float acc[4][4][4];
    #pragma unroll
    for (int mt = 0; mt < 4; mt++)
        #pragma unroll
        for (int nt = 0; nt < 4; nt++)
            #pragma unroll
            for (int q = 0; q < 4; q++) acc[mt][nt][q] = 0.f;

    const int n = tid & 127;
    const int g = tid >> 7;
    const int p = p0 + n;
    const int pr = p / 96;
    const int pc = p - pr*96;
    const uint32_t* y1b = g_y1p + (size_t)b * 64 * PH*PH;

    const int rr  = lid & 7;
    const int sel = lid >> 3;

    for (int tap = 0; tap < 9; tap++) {
        const int kh = tap / 3, kw = tap - 3*(tap/3);
        __syncthreads();

        {
            const __nv_bfloat16* whb = g_wh + ((size_t)((e*9 + tap)*384 + ocb*128))*64;
            const __nv_bfloat16* wlb = g_wl + ((size_t)((e*9 + tap)*384 + ocb*128))*64;
            #pragma unroll
            for (int it = 0; it < 8; it++) {
                int idx = it*256 + tid;
                int s   = idx >> 10;
                int r   = idx & 1023;
                int oc  = r >> 3;
                int ch  = r & 7;
                const __nv_bfloat16* src = (s ? wlb : whb) + oc*64 + ch*8;
                uint4 v = *(const uint4*)src;
                *(uint4*)(smem + s*16384 + SW128((uint32_t)(oc*128 + ch*16))) = v;
            }
        }

        {
            const int ri = pr + kh - 1, ci = pc + kw - 1;
            const bool ok = ((unsigned)ri < 96u) && ((unsigned)ci < 96u);
            const uint32_t* yq = y1b + (size_t)ri*96 + ci;
            #pragma unroll
            for (int j = 0; j < 4; j++) {
                const int ic0 = g*32 + j*8;
                uint32_t pv[8];
                #pragma unroll
                for (int u = 0; u < 8; u++)
                    pv[u] = ok ? __ldg(yq + (size_t)(ic0 + u) * (PH*PH)) : 0u;
                uint32_t hp[4], lp[4];
                #pragma unroll
                for (int u = 0; u < 4; u++) {
                    hp[u] = __byte_perm(pv[2*u], pv[2*u+1], 0x5410);
                    lp[u] = __byte_perm(pv[2*u], pv[2*u+1], 0x7632);
                }
                const uint32_t off = SW128((uint32_t)(n*128 + ic0*2));
                *(uint4*)(smem + 32768 + off) = make_uint4(hp[0], hp[1], hp[2], hp[3]);
                *(uint4*)(smem + 49152 + off) = make_uint4(lp[0], lp[1], lp[2], lp[3]);
            }
        }
        __syncthreads();

        #pragma unroll
        for (int kc = 0; kc < 4; kc++) {
            const int k0b = kc*32;

            uint32_t ah[4][4], al[4][4];
            {
                const int arow = m0w + (sel & 1)*8 + rr;
                const int akb  = k0b + ((sel >> 1)*8)*2;
                #pragma unroll
                for (int mt = 0; mt < 4; mt++) {
                    uint32_t off = SW128((uint32_t)((arow + mt*16)*128 + akb));
                    LDSM4(ah[mt][0], ah[mt][1], ah[mt][2], ah[mt][3], sb + off);
                    LDSM4(al[mt][0], al[mt][1], al[mt][2], al[mt][3], sb + 16384 + off);
                }
            }

            uint32_t bh[4][2], bl[4][2];
            {
                const int brow = n0w + (sel >> 1)*8 + rr;
                const int bkb  = k0b + ((sel & 1)*8)*2;
                #pragma unroll
                for (int pair = 0; pair < 2; pair++) {
                    uint32_t off = SW128((uint32_t)((brow + pair*16)*128 + bkb));
                    LDSM4(bh[pair*2][0], bh[pair*2][1], bh[pair*2+1][0], bh[pair*2+1][1],
                          sb + 32768 + off);
                    LDSM4(bl[pair*2][0], bl[pair*2][1], bl[pair*2+1][0], bl[pair*2+1][1],
                          sb + 49152 + off);
                }
            }

            #pragma unroll
            for (int mt = 0; mt < 4; mt++)
                #pragma unroll
                for (int nt = 0; nt < 4; nt++) {
                    MMA16816(acc[mt][nt], ah[mt], bh[nt][0], bh[nt][1]);
                    MMA16816(acc[mt][nt], ah[mt], bl[nt][0], bl[nt][1]);
                    MMA16816(acc[mt][nt], al[mt], bh[nt][0], bh[nt][1]);
                }
        }
    }

    __syncthreads();
    float* epi = (float*)smem;
    {
        const int r  = lid >> 2;
        const int cc = (lid & 3) * 2;
        #pragma unroll
        for (int mt = 0; mt < 4; mt++)
            #pragma unroll
            for (int nt = 0; nt < 4; nt++) {
                const int m  = m0w + mt*16 + r;
                const int nn = n0w + nt*8 + cc;
                epi[m*128 + nn]         = acc[mt][nt][0];
                epi[m*128 + nn + 1]     = acc[mt][nt][1];
                epi[(m+8)*128 + nn]     = acc[mt][nt][2];
                epi[(m+8)*128 + nn + 1] = acc[mt][nt][3];
            }
    }
    __syncthreads();
    {
        const float* bb = hb1 + e*384 + ocb*128;
        #pragma unroll
        for (int it = 0; it < 16; it++) {
            int i  = it*256 + tid;
            int oc = i >> 5;
            int cx = (i & 31) * 4;
            float4 v = *(float4*)&epi[oc*128 + cx];
            float bias = bb[oc];
            v.x = fmaxf(v.x + bias, 0.f);
            v.y = fmaxf(v.y + bias, 0.f);
            v.z = fmaxf(v.z + bias, 0.f);
            v.w = fmaxf(v.w + bias, 0.f);
            *(float4*)&g_y2[((size_t)(b*384 + ocb*128 + oc))*(PH*PH) + p0 + cx] = v;
        }
    }
}

// =====================================================================
// Kernel 6: grouped 1x1 conv (384 -> 6, groups=3) + bias
// =====================================================================
__global__ void head_conv2(const float* __restrict__ hw2,
                           const float* __restrict__ hb2,
                           float* __restrict__ out)
{
    const int b = blockIdx.z;
    const int g = blockIdx.y;
    const int e = g_idx[b];
    const int tid = threadIdx.x;
    const int p = blockIdx.x * 256 + tid;

    __shared__ float w0s[128], w1s[128];
    if (tid < 128) {
        w0s[tid] = hw2[(e*6 + 2*g)    *128 + tid];
        w1s[tid] = hw2[(e*6 + 2*g + 1)*128 + tid];
    }
    __syncthreads();

    float a0 = hb2[e*6 + 2*g];
    float a1 = hb2[e*6 + 2*g + 1];
    const float* yp = g_y2 + ((size_t)b*384 + g*128) * (PH*PH) + p;
    #pragma unroll 8
    for (int ic = 0; ic < 128; ic++) {
        float v = yp[(size_t)ic * (PH*PH)];
        a0 += v * w0s[ic];
        a1 += v * w1s[ic];
    }
    out[((size_t)b*6 + 2*g)    *(PH*PH) + p] = a0;
    out[((size_t)b*6 + 2*g + 1)*(PH*PH) + p] = a1;
}

// =====================================================================
// launcher
// =====================================================================
extern "C" void kernel_launch(void* const* d_in, const int* in_sizes, int n_in,
                              void* d_out, int out_size)
{
    const float* x        = (const float*)d_in[0];
    const float* g_conv_w = (const float*)d_in[1];
    const float* g_gamma  = (const float*)d_in[2];
    const float* g_beta   = (const float*)d_in[3];
    const float* g_mean   = (const float*)d_in[4];
    const float* g_var    = (const float*)d_in[5];
    const float* g_fc_w   = (const float*)d_in[6];
    const float* g_fc_b   = (const float*)d_in[7];
    const float* e_conv1_w = (const float*)d_in[8];
    const float* e_conv1_b = (const float*)d_in[9];
    const float* e_head_w1 = (const float*)d_in[10];
    const float* e_head_b1 = (const float*)d_in[11];
    const float* e_head_w2 = (const float*)d_in[12];
    const float* e_head_b2 = (const float*)d_in[13];
    float* out = (float*)d_out;

    cudaFuncSetAttribute(head_conv1_mma,
                         cudaFuncAttributeMaxDynamicSharedMemorySize, 65536);
    cudaFuncSetAttribute(gating_mma,
                         cudaFuncAttributeMaxDynamicSharedMemorySize, 65536);
    cudaFuncSetAttribute(expert_mma,
                         cudaFuncAttributeMaxDynamicSharedMemorySize, 65536);

    gw_convert<<<(49*64*16 + 255)/256, 256>>>(g_conv_w);
    ew_convert<<<(NEXP*49*64*16 + 255)/256, 256>>>(e_conv1_w);
    w_convert<<<(NEXP*384*64*9 + 255)/256, 256>>>(e_head_w1);

    dim3 ggate(GH*GH/256, B);                    // 144, 16
    gating_mma<<<ggate, 256, 65536>>>(x, g_gamma, g_beta, g_mean, g_var);

    pool_mean<<<B*64, 256>>>();

    gate_head<<<1, 64>>>(g_fc_w, g_fc_b, out, out_size);

    dim3 gexp(PH*PH/256, B);                     // 36, 16
    expert_mma<<<gexp, 256, 65536>>>(x, e_conv1_b);

    dim3 ghead(PH*PH/128, 3, B);                 // 72, 3, 16
    head_conv1_mma<<<ghead, 256, 65536>>>(e_head_b1);

    dim3 gh2(PH*PH/256, 3, B);                   // 36, 3, 16
    head_conv2<<<gh2, 256>>>(e_head_w2, e_head_b2, out);
}

// round 14
// speedup vs baseline: 1.2109x; 1.0422x over previous
#include <cuda_runtime.h>
#include <cuda_bf16.h>
#include <cuda_fp16.h>
#include <math.h>
#include <stdint.h>

// ---------------- problem constants ----------------
#define B      16
#define CIN    15          // C*T = 3*5
#define HIN    384
#define GH     192         // gating conv out spatial
#define PH     96          // pooled / expert spatial
#define NEXP   3
#define N_OUT  (B*6*PH*PH)   // 884736

// ---------------- device scratch ----------------
__device__ float g_gate[B*64*GH*GH];
__device__ float g_feat[B*64];
__device__ int   g_idx[B];
__device__ uint32_t g_y1p[B*64*PH*PH];          // y1 packed (bf16 lo<<16 | hi), [b][ic][96][96]
__device__ __nv_bfloat16 g_wh[NEXP*9*384*64];   // head w1 hi [e][tap][oc][ic]
__device__ __nv_bfloat16 g_wl[NEXP*9*384*64];   // lo
__device__ __half        g_gwf[49*64*16];       // gating w fp16 [tap][oc][ic16]
__device__ __nv_bfloat16 g_ewh[NEXP*49*64*16];  // expert conv1 w hi [e][tap][oc][ic16]
__device__ __nv_bfloat16 g_ewl[NEXP*49*64*16];

// ---------------- helpers ----------------
__device__ __forceinline__ uint32_t smem_u32(const void* p) {
    uint32_t a;
    asm("{ .reg .u64 t; cvta.to.shared.u64 t, %1; cvt.u32.u64 %0, t; }" : "=r"(a) : "l"(p));
    return a;
}
#define SW128(x) ((x) ^ (((x) >> 3) & 0x70))

__device__ __forceinline__ uint32_t pkbf(__nv_bfloat16 a, __nv_bfloat16 b) {
    __nv_bfloat162 t = __halves2bfloat162(a, b);
    return *reinterpret_cast<uint32_t*>(&t);
}
__device__ __forceinline__ uint32_t pkhf(float a, float b) {
    __half2 t = __floats2half2_rn(a, b);
    return *reinterpret_cast<uint32_t*>(&t);
}
// pack one fp32 value into (bf16_lo << 16) | bf16_hi
__device__ __forceinline__ uint32_t pack_split(float v) {
    __nv_bfloat16 h = __float2bfloat16_rn(v);
    __nv_bfloat16 l = __float2bfloat16_rn(v - __bfloat162float(h));
    return pkbf(h, l);
}

#define LDSM4(r0, r1, r2, r3, a) \
    asm volatile("ldmatrix.sync.aligned.m8n8.x4.shared.b16 {%0,%1,%2,%3}, [%4];" \
        : "=r"(r0), "=r"(r1), "=r"(r2), "=r"(r3) : "r"(a))

#define MMA16816(d, a, b0, b1) \
    asm volatile("mma.sync.aligned.m16n8k16.row.col.f32.bf16.bf16.f32 " \
        "{%0,%1,%2,%3}, {%4,%5,%6,%7}, {%8,%9}, {%0,%1,%2,%3};" \
        : "+f"((d)[0]), "+f"((d)[1]), "+f"((d)[2]), "+f"((d)[3]) \
        : "r"((a)[0]), "r"((a)[1]), "r"((a)[2]), "r"((a)[3]), "r"(b0), "r"(b1))

#define MMA16816F(d, a, b0, b1) \
    asm volatile("mma.sync.aligned.m16n8k16.row.col.f32.f16.f16.f32 " \
        "{%0,%1,%2,%3}, {%4,%5,%6,%7}, {%8,%9}, {%0,%1,%2,%3};" \
        : "+f"((d)[0]), "+f"((d)[1]), "+f"((d)[2]), "+f"((d)[3]) \
        : "r"((a)[0]), "r"((a)[1]), "r"((a)[2]), "r"((a)[3]), "r"(b0), "r"(b1))

// stage-area byte offsets, 48B rows (conflict-free)
#define GSA    0
#define GSB    3072
#define SA_HI 0
#define SA_LO 3072
#define SB_HI 6144
#define SB_LO 18432

// =====================================================================
// weight convert kernels
// =====================================================================
__global__ void gw_convert(const float* __restrict__ w)   // [64][15][7][7] -> fp16
{
    int i = blockIdx.x * 256 + threadIdx.x;
    if (i >= 49*64*16) return;
    int ic = i & 15, oc = (i >> 4) & 63, tap = i >> 10;
    float v = (ic < 15) ? w[oc*735 + ic*49 + tap] : 0.f;
    g_gwf[i] = __float2half_rn(v);
}

__global__ void ew_convert(const float* __restrict__ w)   // [E][64][15][7][7]
{
    int i = blockIdx.x * 256 + threadIdx.x;
    if (i >= NEXP*49*64*16) return;
    int ic = i & 15, oc = (i >> 4) & 63, tap = (i >> 10) % 49, e = i / (49*1024);
    float v = (ic < 15) ? w[((e*64 + oc)*15 + ic)*49 + tap] : 0.f;
    __nv_bfloat16 h = __float2bfloat16_rn(v);
    __nv_bfloat16 l = __float2bfloat16_rn(v - __bfloat162float(h));
    g_ewh[i] = h;
    g_ewl[i] = l;
}

__global__ void w_convert(const float* __restrict__ w)    // head w1 [E][384][64][3][3]
{
    int i = blockIdx.x * 256 + threadIdx.x;
    if (i >= NEXP*384*64*9) return;
    int tap = i % 9;
    int r   = i / 9;
    int ic  = r % 64;
    int r2  = r / 64;
    int oc  = r2 % 384;
    int e   = r2 / 384;
    float v = w[i];
    __nv_bfloat16 h = __float2bfloat16_rn(v);
    __nv_bfloat16 l = __float2bfloat16_rn(v - __bfloat162float(h));
    int dst = ((e*9 + tap)*384 + oc)*64 + ic;
    g_wh[dst] = h;
    g_wl[dst] = l;
}

// =====================================================================
// Kernel 1: gating conv 7x7 s2 p3 (15->64) + BN + ReLU, fp16 single (R11 verified)
// =====================================================================
__global__ void __launch_bounds__(256)
gating_mma(const float* __restrict__ x,
           const float* __restrict__ gamma,
           const float* __restrict__ beta,
           const float* __restrict__ mean,
           const float* __restrict__ var)
{
    extern __shared__ char smem[];
    const uint32_t sb = smem_u32(smem);
    const int tid = threadIdx.x;
    const int wid = tid >> 5, lid = tid & 31;
    const int b   = blockIdx.y;
    const int p0  = blockIdx.x * 256;
    const int n0w = wid * 32;

    float acc[4][4][4];
    #pragma unroll
    for (int mt = 0; mt < 4; mt++)
        #pragma unroll
        for (int nt = 0; nt < 4; nt++)
            #pragma unroll
            for (int q = 0; q < 4; q++) acc[mt][nt][q] = 0.f;

    const int p  = p0 + tid;
    const int oh = p / GH, ow = p - oh*GH;
    const int ih0 = oh*2 - 3, iw0 = ow*2 - 3;
    const float* xb = x + (size_t)b * CIN * HIN * HIN;

    const int rr = lid & 7, sel = lid >> 3;
    const int arow = tid >> 2, apart = tid & 3;

    for (int tap = 0; tap < 49; tap++) {
        const int kh = tap / 7, kw = tap - 7*(tap/7);
        __syncthreads();

        *(uint2*)(smem + GSA + arow*48 + apart*8) =
            *(const uint2*)(g_gwf + tap*1024 + arow*16 + apart*4);

        {
            const int ih = ih0 + kh, iw = iw0 + kw;
            const bool ok = ((unsigned)ih < (unsigned)HIN) && ((unsigned)iw < (unsigned)HIN);
            const float* xq = xb + (size_t)ih*HIN + iw;
            uint32_t hp[8];
            #pragma unroll
            for (int u = 0; u < 16; u += 2) {
                float v0 = (u < 15 && ok)     ? __ldg(xq + (size_t)u     * (HIN*HIN)) : 0.f;
                float v1 = (u + 1 < 15 && ok) ? __ldg(xq + (size_t)(u+1) * (HIN*HIN)) : 0.f;
                hp[u >> 1] = pkhf(v0, v1);
            }
            *(uint4*)(smem + GSB + tid*48)      = make_uint4(hp[0], hp[1], hp[2], hp[3]);
            *(uint4*)(smem + GSB + tid*48 + 16) = make_uint4(hp[4], hp[5], hp[6], hp[7]);
        }
        __syncthreads();

        uint32_t ah[4][4];
        #pragma unroll
        for (int mt = 0; mt < 4; mt++) {
            const uint32_t offA = (mt*16 + (sel & 1)*8 + rr)*48 + (sel >> 1)*16;
            LDSM4(ah[mt][0], ah[mt][1], ah[mt][2], ah[mt][3], sb + GSA + offA);
        }
        uint32_t bh[4][2];
        #pragma unroll
        for (int pair = 0; pair < 2; pair++) {
            const uint32_t offB = (n0w + pair*16 + (sel >> 1)*8 + rr)*48 + (sel & 1)*16;
            LDSM4(bh[pair*2][0], bh[pair*2][1], bh[pair*2+1][0], bh[pair*2+1][1],
                  sb + GSB + offB);
        }
        #pragma unroll
        for (int mt = 0; mt < 4; mt++)
            #pragma unroll
            for (int nt = 0; nt < 4; nt++)
                MMA16816F(acc[mt][nt], ah[mt], bh[nt][0], bh[nt][1]);
    }

    __syncthreads();
    float* epi = (float*)smem;
    {
        const int r  = lid >> 2;
        const int cc = (lid & 3) * 2;
        #pragma unroll
        for (int mt = 0; mt < 4; mt++)
            #pragma unroll
            for (int nt = 0; nt < 4; nt++) {
                const int m  = mt*16 + r;
                const int nn = n0w + nt*8 + cc;
                epi[m*256 + nn]         = acc[mt][nt][0];
                epi[m*256 + nn + 1]     = acc[mt][nt][1];
                epi[(m+8)*256 + nn]     = acc[mt][nt][2];
                epi[(m+8)*256 + nn + 1] = acc[mt][nt][3];
            }
    }
    __syncthreads();
    #pragma unroll
    for (int it = 0; it < 16; it++) {
        int i  = it*256 + tid;
        int oc = i >> 6;
        int cx = (i & 63) * 4;
        float4 v = *(float4*)&epi[oc*256 + cx];
        float inv = gamma[oc] * rsqrtf(var[oc] + 1e-5f);
        float bia = beta[oc] - mean[oc]*inv;
        v.x = fmaxf(v.x*inv + bia, 0.f);
        v.y = fmaxf(v.y*inv + bia, 0.f);
        v.z = fmaxf(v.z*inv + bia, 0.f);
        v.w = fmaxf(v.w*inv + bia, 0.f);
        *(float4*)&g_gate[((size_t)(b*64 + oc))*(GH*GH) + p0 + cx] = v;
    }
}

// =====================================================================
// Kernel 4: expert conv1 7x7 s4 p3 (15->64) + bias + ReLU, bf16 split
// epilogue writes PACKED bf16 hi/lo y1 (R13 verified)
// =====================================================================
__global__ void __launch_bounds__(256)
expert_mma(const float* __restrict__ x,
           const float* __restrict__ eb)
{
    extern __shared__ char smem[];
    const uint32_t sb = smem_u32(smem);
    const int tid = threadIdx.x;
    const int wid = tid >> 5, lid = tid & 31;
    const int b   = blockIdx.y;
    const int e   = g_idx[b];
    const int p0  = blockIdx.x * 256;
    const int n0w = wid * 32;

    float acc[4][4][4];
    #pragma unroll
    for (int mt = 0; mt < 4; mt++)
        #pragma unroll
        for (int nt = 0; nt < 4; nt++)
            #pragma unroll
            for (int q = 0; q < 4; q++) acc[mt][nt][q] = 0.f;

    const int p  = p0 + tid;
    const int oh = p / PH, ow = p - oh*PH;
    const int ih0 = oh*4 - 3, iw0 = ow*4 - 3;
    const float* xb = x + (size_t)b * CIN * HIN * HIN;

    const int rr = lid & 7, sel = lid >> 3;
    const int arow = tid >> 2, apart = tid & 3;
    const __nv_bfloat16* ewh = g_ewh + (size_t)e * 49*1024;
    const __nv_bfloat16* ewl = g_ewl + (size_t)e * 49*1024;

    for (int tap = 0; tap < 49; tap++) {
        const int kh = tap / 7, kw = tap - 7*(tap/7);
        __syncthreads();

        {
            const __nv_bfloat16* sh = ewh + tap*1024 + arow*16 + apart*4;
            const __nv_bfloat16* sl = ewl + tap*1024 + arow*16 + apart*4;
            *(uint2*)(smem + SA_HI + arow*48 + apart*8) = *(const uint2*)sh;
            *(uint2*)(smem + SA_LO + arow*48 + apart*8) = *(const uint2*)sl;
        }
        {
            const int ih = ih0 + kh, iw = iw0 + kw;
            const bool ok = ((unsigned)ih < (unsigned)HIN) && ((unsigned)iw < (unsigned)HIN);
            const float* xq = xb + (size_t)ih*HIN + iw;
            uint32_t hp[8], lp[8];
            #pragma unroll
            for (int u = 0; u < 16; u += 2) {
                float v0 = (u < 15 && ok)     ? __ldg(xq + (size_t)u     * (HIN*HIN)) : 0.f;
                float v1 = (u + 1 < 15 && ok) ? __ldg(xq + (size_t)(u+1) * (HIN*HIN)) : 0.f;
                __nv_bfloat16 h0 = __float2bfloat16_rn(v0);
                __nv_bfloat16 h1 = __float2bfloat16_rn(v1);
                hp[u >> 1] = pkbf(h0, h1);
                __nv_bfloat16 l0 = __float2bfloat16_rn(v0 - __bfloat162float(h0));
                __nv_bfloat16 l1 = __float2bfloat16_rn(v1 - __bfloat162float(h1));
                lp[u >> 1] = pkbf(l0, l1);
            }
            *(uint4*)(smem + SB_HI + tid*48)      = make_uint4(hp[0], hp[1], hp[2], hp[3]);
            *(uint4*)(smem + SB_HI + tid*48 + 16) = make_uint4(hp[4], hp[5], hp[6], hp[7]);
            *(uint4*)(smem + SB_LO + tid*48)      = make_uint4(lp[0], lp[1], lp[2], lp[3]);
            *(uint4*)(smem + SB_LO + tid*48 + 16) = make_uint4(lp[4], lp[5], lp[6], lp[7]);
        }
        __syncthreads();

        uint32_t ah[4][4], al[4][4];
        #pragma unroll
        for (int mt = 0; mt < 4; mt++) {
            const uint32_t offA = (mt*16 + (sel & 1)*8 + rr)*48 + (sel >> 1)*16;
            LDSM4(ah[mt][0], ah[mt][1], ah[mt][2], ah[mt][3], sb + SA_HI + offA);
            LDSM4(al[mt][0], al[mt][1], al[mt][2], al[mt][3], sb + SA_LO + offA);
        }
        uint32_t bh[4][2], bl[4][2];
        #pragma unroll
        for (int pair = 0; pair < 2; pair++) {
            const uint32_t offB = (n0w + pair*16 + (sel >> 1)*8 + rr)*48 + (sel & 1)*16;
            LDSM4(bh[pair*2][0], bh[pair*2][1], bh[pair*2+1][0], bh[pair*2+1][1],
                  sb + SB_HI + offB);
            LDSM4(bl[pair*2][0], bl[pair*2][1], bl[pair*2+1][0], bl[pair*2+1][1],
                  sb + SB_LO + offB);
        }
        #pragma unroll
        for (int mt = 0; mt < 4; mt++)
            #pragma unroll
            for (int nt = 0; nt < 4; nt++) {
                MMA16816(acc[mt][nt], ah[mt], bh[nt][0], bh[nt][1]);
                MMA16816(acc[mt][nt], ah[mt], bl[nt][0], bl[nt][1]);
                MMA16816(acc[mt][nt], al[mt], bh[nt][0], bh[nt][1]);
            }
    }

    __syncthreads();
    float* epi = (float*)smem;
    {
        const int r  = lid >> 2;
        const int cc = (lid & 3) * 2;
        #pragma unroll
        for (int mt = 0; mt < 4; mt++)
            #pragma unroll
            for (int nt = 0; nt < 4; nt++) {
                const int m  = mt*16 + r;
                const int nn = n0w + nt*8 + cc;
                epi[m*256 + nn]         = acc[mt][nt][0];
                epi[m*256 + nn + 1]     = acc[mt][nt][1];
                epi[(m+8)*256 + nn]     = acc[mt][nt][2];
                epi[(m+8)*256 + nn + 1] = acc[mt][nt][3];
            }
    }
    __syncthreads();
    const float* bb = eb + e*64;
    #pragma unroll
    for (int it = 0; it < 16; it++) {
        int i  = it*256 + tid;
        int oc = i >> 6;
        int cx = (i & 63) * 4;
        float4 v = *(float4*)&epi[oc*256 + cx];
        float bias = bb[oc];
        v.x = fmaxf(v.x + bias, 0.f);
        v.y = fmaxf(v.y + bias, 0.f);
        v.z = fmaxf(v.z + bias, 0.f);
        v.w = fmaxf(v.w + bias, 0.f);
        uint4 pk;
        pk.x = pack_split(v.x);
        pk.y = pack_split(v.y);
        pk.z = pack_split(v.z);
        pk.w = pack_split(v.w);
        *(uint4*)&g_y1p[((size_t)(b*64 + oc))*(PH*PH) + p0 + cx] = pk;
    }
}

// =====================================================================
// Kernel 2: maxpool 3x3 s2 p1 + spatial mean
// =====================================================================
__global__ void pool_mean()
{
    const int bc = blockIdx.x;
    const float* src = g_gate + (size_t)bc * GH * GH;
    const int tid = threadIdx.x;
    float sum = 0.f;
    for (int p = tid; p < PH*PH; p += 256) {
        int ph = p / PH, pw = p - ph*PH;
        float m = -1e30f;
        #pragma unroll
        for (int r = 0; r < 3; r++) {
            int ih = 2*ph - 1 + r;
            if ((unsigned)ih >= (unsigned)GH) continue;
            #pragma unroll
            for (int c = 0; c < 3; c++) {
                int iw = 2*pw - 1 + c;
                if ((unsigned)iw >= (unsigned)GH) continue;
                m = fmaxf(m, src[ih*GH + iw]);
            }
        }
        sum += m;
    }
    __shared__ float red[256];
    red[tid] = sum;
    __syncthreads();
    for (int s = 128; s > 0; s >>= 1) {
        if (tid < s) red[tid] += red[tid + s];
        __syncthreads();
    }
    if (tid == 0) g_feat[bc] = red[0] / (float)(PH*PH);
}

// =====================================================================
// Kernel 3: logits, argmax, aux loss
// =====================================================================
__global__ void gate_head(const float* __restrict__ fcw,
                          const float* __restrict__ fcb,
                          float* __restrict__ out, int out_size)
{
    __shared__ float lg[B][NEXP];
    __shared__ float proxy[NEXP];
    __shared__ int   cnt[NEXP];
    const int t = threadIdx.x;

    if (t < NEXP) { proxy[t] = 0.f; cnt[t] = 0; }
    if (t < B*NEXP) {
        int b = t / NEXP, e = t - b*NEXP;
        float s = fcb[e];
        const float* f = g_feat + b*64;
        const float* wr = fcw + e*64;
        for (int c = 0; c < 64; c++) s += f[c]*wr[c];
        lg[b][e] = s;
    }
    __syncthreads();
    if (t < B) {
        float l0 = lg[t][0], l1 = lg[t][1], l2 = lg[t][2];
        int am = 0; float bm = l0;
        if (l1 > bm) { bm = l1; am = 1; }
        if (l2 > bm) { bm = l2; am = 2; }
        g_idx[t] = am;
        atomicAdd(&cnt[am], 1);
        float m = bm;
        float e0 = expf(l0 - m), e1 = expf(l1 - m), e2 = expf(l2 - m);
        float s = e0 + e1 + e2;
        atomicAdd(&proxy[0], e0/s);
        atomicAdd(&proxy[1], e1/s);
        atomicAdd(&proxy[2], e2/s);
    }
    __syncthreads();
    if (t == 0 && out_size > N_OUT) {
        float aux = 0.f;
        for (int e = 0; e < NEXP; e++)
            aux += ((float)cnt[e] / (float)B) * (proxy[e] / (float)B);
        out[N_OUT] = 0.01f * (aux * (float)NEXP);
    }
}

// =====================================================================
// Kernel 5: FUSED head conv1 3x3 (64->384) + grouped 1x1 (->2 ch per ocb) + out
// Mainloop identical to R13 head_conv1_mma; epilogue computes head_conv2 in-CTA.
// CTA (px-tile, ocb, b) owns oc [ocb*128, ocb*128+128) == group ocb of the 1x1,
// producing output channels 2*ocb, 2*ocb+1 for its 128 pixels.
// =====================================================================
__global__ void __launch_bounds__(256)
head_fused_mma(const float* __restrict__ hb1,
               const float* __restrict__ hw2,
               const float* __restrict__ hb2,
               float* __restrict__ out)
{
    extern __shared__ char smem[];
    __shared__ float w0s[128], w1s[128], b1s[128];
    __shared__ float red0[256], red1[256];
    const uint32_t sb = smem_u32(smem);
    const int tid = threadIdx.x;
    const int wid = tid >> 5, lid = tid & 31;
    const int b   = blockIdx.z;
    const int ocb = blockIdx.y;
    const int p0  = blockIdx.x * 128;
    const int e   = g_idx[b];

    // load 1x1 weights + conv bias for this oc-block
    if (tid < 128) {
        w0s[tid] = hw2[(e*6 + 2*ocb)*128 + tid];
        b1s[tid] = hb1[e*384 + ocb*128 + tid];
    } else {
        w1s[tid - 128] = hw2[(e*6 + 2*ocb + 1)*128 + (tid - 128)];
    }

    const int warpM = wid >> 2, warpN = wid & 3;
    const int m0w = warpM * 64, n0w = warpN * 32;

    float acc[4][4][4];
    #pragma unroll
    for (int mt = 0; mt < 4; mt++)
        #pragma unroll
        for (int nt = 0; nt < 4; nt++)
            #pragma unroll
            for (int q = 0; q < 4; q++) acc[mt][nt][q] = 0.f;

    const int n = tid & 127;
    const int g = tid >> 7;
    const int p = p0 + n;
    const int pr = p / 96;
    const int pc = p - pr*96;
    const uint32_t* y1b = g_y1p + (size_t)b * 64 * PH*PH;

    const int rr  = lid & 7;
    const int sel = lid >> 3;

    for (int tap = 0; tap < 9; tap++) {
        const int kh = tap / 3, kw = tap - 3*(tap/3);
        __syncthreads();

        {
            const __nv_bfloat16* whb = g_wh + ((size_t)((e*9 + tap)*384 + ocb*128))*64;
            const __nv_bfloat16* wlb = g_wl + ((size_t)((e*9 + tap)*384 + ocb*128))*64;
            #pragma unroll
            for (int it = 0; it < 8; it++) {
                int idx = it*256 + tid;
                int s   = idx >> 10;
                int r   = idx & 1023;
                int oc  = r >> 3;
                int ch  = r & 7;
                const __nv_bfloat16* src = (s ? wlb : whb) + oc*64 + ch*8;
                uint4 v = *(const uint4*)src;
                *(uint4*)(smem + s*16384 + SW128((uint32_t)(oc*128 + ch*16))) = v;
            }
        }

        {
            const int ri = pr + kh - 1, ci = pc + kw - 1;
            const bool ok = ((unsigned)ri < 96u) && ((unsigned)ci < 96u);
            const uint32_t* yq = y1b + (size_t)ri*96 + ci;
            #pragma unroll
            for (int j = 0; j < 4; j++) {
                const int ic0 = g*32 + j*8;
                uint32_t pv[8];
                #pragma unroll
                for (int u = 0; u < 8; u++)
                    pv[u] = ok ? __ldg(yq + (size_t)(ic0 + u) * (PH*PH)) : 0u;
                uint32_t hp[4], lp[4];
                #pragma unroll
                for (int u = 0; u < 4; u++) {
                    hp[u] = __byte_perm(pv[2*u], pv[2*u+1], 0x5410);
                    lp[u] = __byte_perm(pv[2*u], pv[2*u+1], 0x7632);
                }
                const uint32_t off = SW128((uint32_t)(n*128 + ic0*2));
                *(uint4*)(smem + 32768 + off) = make_uint4(hp[0], hp[1], hp[2], hp[3]);
                *(uint4*)(smem + 49152 + off) = make_uint4(lp[0], lp[1], lp[2], lp[3]);
            }
        }
        __syncthreads();

        #pragma unroll
        for (int kc = 0; kc < 4; kc++) {
            const int k0b = kc*32;

            uint32_t ah[4][4], al[4][4];
            {
                const int arow = m0w + (sel & 1)*8 + rr;
                const int akb  = k0b + ((sel >> 1)*8)*2;
                #pragma unroll
                for (int mt = 0; mt < 4; mt++) {
                    uint32_t off = SW128((uint32_t)((arow + mt*16)*128 + akb));
                    LDSM4(ah[mt][0], ah[mt][1], ah[mt][2], ah[mt][3], sb + off);
                    LDSM4(al[mt][0], al[mt][1], al[mt][2], al[mt][3], sb + 16384 + off);
                }
            }

            uint32_t bh[4][2], bl[4][2];
            {
                const int brow = n0w + (sel >> 1)*8 + rr;
                const int bkb  = k0b + ((sel & 1)*8)*2;
                #pragma unroll
                for (int pair = 0; pair < 2; pair++) {
                    uint32_t off = SW128((uint32_t)((brow + pair*16)*128 + bkb));
                    LDSM4(bh[pair*2][0], bh[pair*2][1], bh[pair*2+1][0], bh[pair*2+1][1],
                          sb + 32768 + off);
                    LDSM4(bl[pair*2][0], bl[pair*2][1], bl[pair*2+1][0], bl[pair*2+1][1],
                          sb + 49152 + off);
                }
            }

            #pragma unroll
            for (int mt = 0; mt < 4; mt++)
                #pragma unroll
                for (int nt = 0; nt < 4; nt++) {
                    MMA16816(acc[mt][nt], ah[mt], bh[nt][0], bh[nt][1]);
                    MMA16816(acc[mt][nt], ah[mt], bl[nt][0], bl[nt][1]);
                    MMA16816(acc[mt][nt], al[mt], bh[nt][0], bh[nt][1]);
                }
        }
    }

    // ---- fused epilogue: acc -> epi smem [128 oc][128 px], then 1x1 conv -> out
    __syncthreads();
    float* epi = (float*)smem;
    {
        const int r  = lid >> 2;
        const int cc = (lid & 3) * 2;
        #pragma unroll
        for (int mt = 0; mt < 4; mt++)
            #pragma unroll
            for (int nt = 0; nt < 4; nt++) {
                const int m  = m0w + mt*16 + r;
                const int nn = n0w + nt*8 + cc;
                epi[m*128 + nn]         = acc[mt][nt][0];
                epi[m*128 + nn + 1]     = acc[mt][nt][1];
                epi[(m+8)*128 + nn]     = acc[mt][nt][2];
                epi[(m+8)*128 + nn + 1] = acc[mt][nt][3];
            }
    }
    __syncthreads();
    {
        const int px = tid & 127;
        const int h  = tid >> 7;
        float s0 = 0.f, s1 = 0.f;
        #pragma unroll 8
        for (int j = 0; j < 64; j++) {
            const int oc = h*64 + j;
            float v = fmaxf(epi[oc*128 + px] + b1s[oc], 0.f);
            s0 += v * w0s[oc];
            s1 += v * w1s[oc];
        }
        red0[tid] = s0;
        red1[tid] = s1;
    }
    __syncthreads();
    if (tid < 128) {
        const int px = tid;
        float o0 = hb2[e*6 + 2*ocb]     + red0[px] + red0[128 + px];
        float o1 = hb2[e*6 + 2*ocb + 1] + red1[px] + red1[128 + px];
        out[((size_t)(b*6 + 2*ocb))    *(PH*PH) + p0 + px] = o0;
        out[((size_t)(b*6 + 2*ocb + 1))*(PH*PH) + p0 + px] = o1;
    }
}

// =====================================================================
// launcher
// =====================================================================
extern "C" void kernel_launch(void* const* d_in, const int* in_sizes, int n_in,
                              void* d_out, int out_size)
{
    const float* x        = (const float*)d_in[0];
    const float* g_conv_w = (const float*)d_in[1];
    const float* g_gamma  = (const float*)d_in[2];
    const float* g_beta   = (const float*)d_in[3];
    const float* g_mean   = (const float*)d_in[4];
    const float* g_var    = (const float*)d_in[5];
    const float* g_fc_w   = (const float*)d_in[6];
    const float* g_fc_b   = (const float*)d_in[7];
    const float* e_conv1_w = (const float*)d_in[8];
    const float* e_conv1_b = (const float*)d_in[9];
    const float* e_head_w1 = (const float*)d_in[10];
    const float* e_head_b1 = (const float*)d_in[11];
    const float* e_head_w2 = (const float*)d_in[12];
    const float* e_head_b2 = (const float*)d_in[13];
    float* out = (float*)d_out;

    cudaFuncSetAttribute(head_fused_mma,
                         cudaFuncAttributeMaxDynamicSharedMemorySize, 65536);
    cudaFuncSetAttribute(gating_mma,
                         cudaFuncAttributeMaxDynamicSharedMemorySize, 65536);
    cudaFuncSetAttribute(expert_mma,
                         cudaFuncAttributeMaxDynamicSharedMemorySize, 65536);

    gw_convert<<<(49*64*16 + 255)/256, 256>>>(g_conv_w);
    ew_convert<<<(NEXP*49*64*16 + 255)/256, 256>>>(e_conv1_w);
    w_convert<<<(NEXP*384*64*9 + 255)/256, 256>>>(e_head_w1);

    dim3 ggate(GH*GH/256, B);                    // 144, 16
    gating_mma<<<ggate, 256, 65536>>>(x, g_gamma, g_beta, g_mean, g_var);

    pool_mean<<<B*64, 256>>>();

    gate_head<<<1, 64>>>(g_fc_w, g_fc_b, out, out_size);

    dim3 gexp(PH*PH/256, B);                     // 36, 16
    expert_mma<<<gexp, 256, 65536>>>(x, e_conv1_b);

    dim3 ghead(PH*PH/128, 3, B);                 // 72, 3, 16
    head_fused_mma<<<ghead, 256, 65536>>>(e_head_b1, e_head_w2, e_head_b2, out);
}

// round 15
// speedup vs baseline: 1.2417x; 1.0254x over previous
#include <cuda_runtime.h>
#include <cuda_bf16.h>
#include <cuda_fp16.h>
#include <math.h>
#include <stdint.h>

// ---------------- problem constants ----------------
#define B      16
#define CIN    15          // C*T = 3*5
#define HIN    384
#define GH     192         // gating conv out spatial
#define PH     96          // pooled / expert spatial
#define NEXP   3
#define N_OUT  (B*6*PH*PH)   // 884736

// ---------------- device scratch ----------------
__device__ float g_gate[B*64*GH*GH];
__device__ float g_feat[B*64];
__device__ int   g_idx[B];
__device__ uint32_t g_y1p[B*64*PH*PH];          // y1 packed (bf16 lo<<16 | hi), [b][ic][96][96]
__device__ __nv_bfloat16 g_wh[NEXP*9*384*64];   // head w1 hi [e][tap][oc][ic]
__device__ __nv_bfloat16 g_wl[NEXP*9*384*64];   // lo
__device__ __half        g_gwf[49*64*16];       // gating w fp16 [tap][oc][ic16]
__device__ __nv_bfloat16 g_ewh[NEXP*49*64*16];  // expert conv1 w hi [e][tap][oc][ic16]
__device__ __nv_bfloat16 g_ewl[NEXP*49*64*16];

// ---------------- helpers ----------------
__device__ __forceinline__ uint32_t smem_u32(const void* p) {
    uint32_t a;
    asm("{ .reg .u64 t; cvta.to.shared.u64 t, %1; cvt.u32.u64 %0, t; }" : "=r"(a) : "l"(p));
    return a;
}
#define SW128(x) ((x) ^ (((x) >> 3) & 0x70))

__device__ __forceinline__ uint32_t pkbf(__nv_bfloat16 a, __nv_bfloat16 b) {
    __nv_bfloat162 t = __halves2bfloat162(a, b);
    return *reinterpret_cast<uint32_t*>(&t);
}
__device__ __forceinline__ uint32_t pkhf(float a, float b) {
    __half2 t = __floats2half2_rn(a, b);
    return *reinterpret_cast<uint32_t*>(&t);
}
// pack one fp32 value into (bf16_lo << 16) | bf16_hi
__device__ __forceinline__ uint32_t pack_split(float v) {
    __nv_bfloat16 h = __float2bfloat16_rn(v);
    __nv_bfloat16 l = __float2bfloat16_rn(v - __bfloat162float(h));
    return pkbf(h, l);
}

#define LDSM4(r0, r1, r2, r3, a) \
    asm volatile("ldmatrix.sync.aligned.m8n8.x4.shared.b16 {%0,%1,%2,%3}, [%4];" \
        : "=r"(r0), "=r"(r1), "=r"(r2), "=r"(r3) : "r"(a))

#define MMA16816(d, a, b0, b1) \
    asm volatile("mma.sync.aligned.m16n8k16.row.col.f32.bf16.bf16.f32 " \
        "{%0,%1,%2,%3}, {%4,%5,%6,%7}, {%8,%9}, {%0,%1,%2,%3};" \
        : "+f"((d)[0]), "+f"((d)[1]), "+f"((d)[2]), "+f"((d)[3]) \
        : "r"((a)[0]), "r"((a)[1]), "r"((a)[2]), "r"((a)[3]), "r"(b0), "r"(b1))

#define MMA16816F(d, a, b0, b1) \
    asm volatile("mma.sync.aligned.m16n8k16.row.col.f32.f16.f16.f32 " \
        "{%0,%1,%2,%3}, {%4,%5,%6,%7}, {%8,%9}, {%0,%1,%2,%3};" \
        : "+f"((d)[0]), "+f"((d)[1]), "+f"((d)[2]), "+f"((d)[3]) \
        : "r"((a)[0]), "r"((a)[1]), "r"((a)[2]), "r"((a)[3]), "r"(b0), "r"(b1))

// stage-area byte offsets, 48B rows (conflict-free)
#define GSA    0
#define GSB    3072
#define SA_HI 0
#define SA_LO 3072
#define SB_HI 6144
#define SB_LO 18432

// =====================================================================
// weight convert kernels
// =====================================================================
__global__ void gw_convert(const float* __restrict__ w)   // [64][15][7][7] -> fp16
{
    int i = blockIdx.x * 256 + threadIdx.x;
    if (i >= 49*64*16) return;
    int ic = i & 15, oc = (i >> 4) & 63, tap = i >> 10;
    float v = (ic < 15) ? w[oc*735 + ic*49 + tap] : 0.f;
    g_gwf[i] = __float2half_rn(v);
}

__global__ void ew_convert(const float* __restrict__ w)   // [E][64][15][7][7]
{
    int i = blockIdx.x * 256 + threadIdx.x;
    if (i >= NEXP*49*64*16) return;
    int ic = i & 15, oc = (i >> 4) & 63, tap = (i >> 10) % 49, e = i / (49*1024);
    float v = (ic < 15) ? w[((e*64 + oc)*15 + ic)*49 + tap] : 0.f;
    __nv_bfloat16 h = __float2bfloat16_rn(v);
    __nv_bfloat16 l = __float2bfloat16_rn(v - __bfloat162float(h));
    g_ewh[i] = h;
    g_ewl[i] = l;
}

__global__ void w_convert(const float* __restrict__ w)    // head w1 [E][384][64][3][3]
{
    int i = blockIdx.x * 256 + threadIdx.x;
    if (i >= NEXP*384*64*9) return;
    int tap = i % 9;
    int r   = i / 9;
    int ic  = r % 64;
    int r2  = r / 64;
    int oc  = r2 % 384;
    int e   = r2 / 384;
    float v = w[i];
    __nv_bfloat16 h = __float2bfloat16_rn(v);
    __nv_bfloat16 l = __float2bfloat16_rn(v - __bfloat162float(h));
    int dst = ((e*9 + tap)*384 + oc)*64 + ic;
    g_wh[dst] = h;
    g_wl[dst] = l;
}

// =====================================================================
// Kernel 1: gating conv 7x7 s2 p3 (15->64) + BN + ReLU, fp16 single
// R11 mainloop verbatim; epilogue split into two 32-oc chunks so dynamic
// smem = 32 KB -> 2 CTAs/SM (cross-CTA overlap of staging and MMA phases)
// =====================================================================
__global__ void __launch_bounds__(256, 2)
gating_mma(const float* __restrict__ x,
           const float* __restrict__ gamma,
           const float* __restrict__ beta,
           const float* __restrict__ mean,
           const float* __restrict__ var)
{
    extern __shared__ char smem[];
    const uint32_t sb = smem_u32(smem);
    const int tid = threadIdx.x;
    const int wid = tid >> 5, lid = tid & 31;
    const int b   = blockIdx.y;
    const int p0  = blockIdx.x * 256;
    const int n0w = wid * 32;

    float acc[4][4][4];
    #pragma unroll
    for (int mt = 0; mt < 4; mt++)
        #pragma unroll
        for (int nt = 0; nt < 4; nt++)
            #pragma unroll
            for (int q = 0; q < 4; q++) acc[mt][nt][q] = 0.f;

    const int p  = p0 + tid;
    const int oh = p / GH, ow = p - oh*GH;
    const int ih0 = oh*2 - 3, iw0 = ow*2 - 3;
    const float* xb = x + (size_t)b * CIN * HIN * HIN;

    const int rr = lid & 7, sel = lid >> 3;
    const int arow = tid >> 2, apart = tid & 3;

    for (int tap = 0; tap < 49; tap++) {
        const int kh = tap / 7, kw = tap - 7*(tap/7);
        __syncthreads();

        *(uint2*)(smem + GSA + arow*48 + apart*8) =
            *(const uint2*)(g_gwf + tap*1024 + arow*16 + apart*4);

        {
            const int ih = ih0 + kh, iw = iw0 + kw;
            const bool ok = ((unsigned)ih < (unsigned)HIN) && ((unsigned)iw < (unsigned)HIN);
            const float* xq = xb + (size_t)ih*HIN + iw;
            uint32_t hp[8];
            #pragma unroll
            for (int u = 0; u < 16; u += 2) {
                float v0 = (u < 15 && ok)     ? __ldg(xq + (size_t)u     * (HIN*HIN)) : 0.f;
                float v1 = (u + 1 < 15 && ok) ? __ldg(xq + (size_t)(u+1) * (HIN*HIN)) : 0.f;
                hp[u >> 1] = pkhf(v0, v1);
            }
            *(uint4*)(smem + GSB + tid*48)      = make_uint4(hp[0], hp[1], hp[2], hp[3]);
            *(uint4*)(smem + GSB + tid*48 + 16) = make_uint4(hp[4], hp[5], hp[6], hp[7]);
        }
        __syncthreads();

        uint32_t ah[4][4];
        #pragma unroll
        for (int mt = 0; mt < 4; mt++) {
            const uint32_t offA = (mt*16 + (sel & 1)*8 + rr)*48 + (sel >> 1)*16;
            LDSM4(ah[mt][0], ah[mt][1], ah[mt][2], ah[mt][3], sb + GSA + offA);
        }
        uint32_t bh[4][2];
        #pragma unroll
        for (int pair = 0; pair < 2; pair++) {
            const uint32_t offB = (n0w + pair*16 + (sel >> 1)*8 + rr)*48 + (sel & 1)*16;
            LDSM4(bh[pair*2][0], bh[pair*2][1], bh[pair*2+1][0], bh[pair*2+1][1],
                  sb + GSB + offB);
        }
        #pragma unroll
        for (int mt = 0; mt < 4; mt++)
            #pragma unroll
            for (int nt = 0; nt < 4; nt++)
                MMA16816F(acc[mt][nt], ah[mt], bh[nt][0], bh[nt][1]);
    }

    // epilogue: two 32-oc chunks via smem float[32][256] (32 KB)
    float* epi = (float*)smem;
    #pragma unroll
    for (int half = 0; half < 2; half++) {
        __syncthreads();
        {
            const int r  = lid >> 2;
            const int cc = (lid & 3) * 2;
            #pragma unroll
            for (int mtl = 0; mtl < 2; mtl++) {
                const int mt = half*2 + mtl;
                #pragma unroll
                for (int nt = 0; nt < 4; nt++) {
                    const int m  = mtl*16 + r;
                    const int nn = n0w + nt*8 + cc;
                    epi[m*256 + nn]         = acc[mt][nt][0];
                    epi[m*256 + nn + 1]     = acc[mt][nt][1];
                    epi[(m+8)*256 + nn]     = acc[mt][nt][2];
                    epi[(m+8)*256 + nn + 1] = acc[mt][nt][3];
                }
            }
        }
        __syncthreads();
        #pragma unroll
        for (int it = 0; it < 8; it++) {
            int i   = it*256 + tid;          // uint4 index within chunk
            int ocl = i >> 6;
            int oc  = half*32 + ocl;
            int cx  = (i & 63) * 4;
            float4 v = *(float4*)&epi[ocl*256 + cx];
            float inv = gamma[oc] * rsqrtf(var[oc] + 1e-5f);
            float bia = beta[oc] - mean[oc]*inv;
            v.x = fmaxf(v.x*inv + bia, 0.f);
            v.y = fmaxf(v.y*inv + bia, 0.f);
            v.z = fmaxf(v.z*inv + bia, 0.f);
            v.w = fmaxf(v.w*inv + bia, 0.f);
            *(float4*)&g_gate[((size_t)(b*64 + oc))*(GH*GH) + p0 + cx] = v;
        }
    }
}

// =====================================================================
// Kernel 4: expert conv1 7x7 s4 p3 (15->64) + bias + ReLU, bf16 split
// epilogue writes PACKED bf16 hi/lo y1 (R13 verified)
// =====================================================================
__global__ void __launch_bounds__(256)
expert_mma(const float* __restrict__ x,
           const float* __restrict__ eb)
{
    extern __shared__ char smem[];
    const uint32_t sb = smem_u32(smem);
    const int tid = threadIdx.x;
    const int wid = tid >> 5, lid = tid & 31;
    const int b   = blockIdx.y;
    const int e   = g_idx[b];
    const int p0  = blockIdx.x * 256;
    const int n0w = wid * 32;

    float acc[4][4][4];
    #pragma unroll
    for (int mt = 0; mt < 4; mt++)
        #pragma unroll
        for (int nt = 0; nt < 4; nt++)
            #pragma unroll
            for (int q = 0; q < 4; q++) acc[mt][nt][q] = 0.f;

    const int p  = p0 + tid;
    const int oh = p / PH, ow = p - oh*PH;
    const int ih0 = oh*4 - 3, iw0 = ow*4 - 3;
    const float* xb = x + (size_t)b * CIN * HIN * HIN;

    const int rr = lid & 7, sel = lid >> 3;
    const int arow = tid >> 2, apart = tid & 3;
    const __nv_bfloat16* ewh = g_ewh + (size_t)e * 49*1024;
    const __nv_bfloat16* ewl = g_ewl + (size_t)e * 49*1024;

    for (int tap = 0; tap < 49; tap++) {
        const int kh = tap / 7, kw = tap - 7*(tap/7);
        __syncthreads();

        {
            const __nv_bfloat16* sh = ewh + tap*1024 + arow*16 + apart*4;
            const __nv_bfloat16* sl = ewl + tap*1024 + arow*16 + apart*4;
            *(uint2*)(smem + SA_HI + arow*48 + apart*8) = *(const uint2*)sh;
            *(uint2*)(smem + SA_LO + arow*48 + apart*8) = *(const uint2*)sl;
        }
        {
            const int ih = ih0 + kh, iw = iw0 + kw;
            const bool ok = ((unsigned)ih < (unsigned)HIN) && ((unsigned)iw < (unsigned)HIN);
            const float* xq = xb + (size_t)ih*HIN + iw;
            uint32_t hp[8], lp[8];
            #pragma unroll
            for (int u = 0; u < 16; u += 2) {
                float v0 = (u < 15 && ok)     ? __ldg(xq + (size_t)u     * (HIN*HIN)) : 0.f;
                float v1 = (u + 1 < 15 && ok) ? __ldg(xq + (size_t)(u+1) * (HIN*HIN)) : 0.f;
                __nv_bfloat16 h0 = __float2bfloat16_rn(v0);
                __nv_bfloat16 h1 = __float2bfloat16_rn(v1);
                hp[u >> 1] = pkbf(h0, h1);
                __nv_bfloat16 l0 = __float2bfloat16_rn(v0 - __bfloat162float(h0));
                __nv_bfloat16 l1 = __float2bfloat16_rn(v1 - __bfloat162float(h1));
                lp[u >> 1] = pkbf(l0, l1);
            }
            *(uint4*)(smem + SB_HI + tid*48)      = make_uint4(hp[0], hp[1], hp[2], hp[3]);
            *(uint4*)(smem + SB_HI + tid*48 + 16) = make_uint4(hp[4], hp[5], hp[6], hp[7]);
            *(uint4*)(smem + SB_LO + tid*48)      = make_uint4(lp[0], lp[1], lp[2], lp[3]);
            *(uint4*)(smem + SB_LO + tid*48 + 16) = make_uint4(lp[4], lp[5], lp[6], lp[7]);
        }
        __syncthreads();

        uint32_t ah[4][4], al[4][4];
        #pragma unroll
        for (int mt = 0; mt < 4; mt++) {
            const uint32_t offA = (mt*16 + (sel & 1)*8 + rr)*48 + (sel >> 1)*16;
            LDSM4(ah[mt][0], ah[mt][1], ah[mt][2], ah[mt][3], sb + SA_HI + offA);
            LDSM4(al[mt][0], al[mt][1], al[mt][2], al[mt][3], sb + SA_LO + offA);
        }
        uint32_t bh[4][2], bl[4][2];
        #pragma unroll
        for (int pair = 0; pair < 2; pair++) {
            const uint32_t offB = (n0w + pair*16 + (sel >> 1)*8 + rr)*48 + (sel & 1)*16;
            LDSM4(bh[pair*2][0], bh[pair*2][1], bh[pair*2+1][0], bh[pair*2+1][1],
                  sb + SB_HI + offB);
            LDSM4(bl[pair*2][0], bl[pair*2][1], bl[pair*2+1][0], bl[pair*2+1][1],
                  sb + SB_LO + offB);
        }
        #pragma unroll
        for (int mt = 0; mt < 4; mt++)
            #pragma unroll
            for (int nt = 0; nt < 4; nt++) {
                MMA16816(acc[mt][nt], ah[mt], bh[nt][0], bh[nt][1]);
                MMA16816(acc[mt][nt], ah[mt], bl[nt][0], bl[nt][1]);
                MMA16816(acc[mt][nt], al[mt], bh[nt][0], bh[nt][1]);
            }
    }

    __syncthreads();
    float* epi = (float*)smem;
    {
        const int r  = lid >> 2;
        const int cc = (lid & 3) * 2;
        #pragma unroll
        for (int mt = 0; mt < 4; mt++)
            #pragma unroll
            for (int nt = 0; nt < 4; nt++) {
                const int m  = mt*16 + r;
                const int nn = n0w + nt*8 + cc;
                epi[m*256 + nn]         = acc[mt][nt][0];
                epi[m*256 + nn + 1]     = acc[mt][nt][1];
                epi[(m+8)*256 + nn]     = acc[mt][nt][2];
                epi[(m+8)*256 + nn + 1] = acc[mt][nt][3];
            }
    }
    __syncthreads();
    const float* bb = eb + e*64;
    #pragma unroll
    for (int it = 0; it < 16; it++) {
        int i  = it*256 + tid;
        int oc = i >> 6;
        int cx = (i & 63) * 4;
        float4 v = *(float4*)&epi[oc*256 + cx];
        float bias = bb[oc];
        v.x = fmaxf(v.x + bias, 0.f);
        v.y = fmaxf(v.y + bias, 0.f);
        v.z = fmaxf(v.z + bias, 0.f);
        v.w = fmaxf(v.w + bias, 0.f);
        uint4 pk;
        pk.x = pack_split(v.x);
        pk.y = pack_split(v.y);
        pk.z = pack_split(v.z);
        pk.w = pack_split(v.w);
        *(uint4*)&g_y1p[((size_t)(b*64 + oc))*(PH*PH) + p0 + cx] = pk;
    }
}

// =====================================================================
// Kernel 2: maxpool 3x3 s2 p1 + spatial mean
// =====================================================================
__global__ void pool_mean()
{
    const int bc = blockIdx.x;
    const float* src = g_gate + (size_t)bc * GH * GH;
    const int tid = threadIdx.x;
    float sum = 0.f;
    for (int p = tid; p < PH*PH; p += 256) {
        int ph = p / PH, pw = p - ph*PH;
        float m = -1e30f;
        #pragma unroll
        for (int r = 0; r < 3; r++) {
            int ih = 2*ph - 1 + r;
            if ((unsigned)ih >= (unsigned)GH) continue;
            #pragma unroll
            for (int c = 0; c < 3; c++) {
                int iw = 2*pw - 1 + c;
                if ((unsigned)iw >= (unsigned)GH) continue;
                m = fmaxf(m, src[ih*GH + iw]);
            }
        }
        sum += m;
    }
    __shared__ float red[256];
    red[tid] = sum;
    __syncthreads();
    for (int s = 128; s > 0; s >>= 1) {
        if (tid < s) red[tid] += red[tid + s];
        __syncthreads();
    }
    if (tid == 0) g_feat[bc] = red[0] / (float)(PH*PH);
}

// =====================================================================
// Kernel 3: logits, argmax, aux loss
// =====================================================================
__global__ void gate_head(const float* __restrict__ fcw,
                          const float* __restrict__ fcb,
                          float* __restrict__ out, int out_size)
{
    __shared__ float lg[B][NEXP];
    __shared__ float proxy[NEXP];
    __shared__ int   cnt[NEXP];
    const int t = threadIdx.x;

    if (t < NEXP) { proxy[t] = 0.f; cnt[t] = 0; }
    if (t < B*NEXP) {
        int b = t / NEXP, e = t - b*NEXP;
        float s = fcb[e];
        const float* f = g_feat + b*64;
        const float* wr = fcw + e*64;
        for (int c = 0; c < 64; c++) s += f[c]*wr[c];
        lg[b][e] = s;
    }
    __syncthreads();
    if (t < B) {
        float l0 = lg[t][0], l1 = lg[t][1], l2 = lg[t][2];
        int am = 0; float bm = l0;
        if (l1 > bm) { bm = l1; am = 1; }
        if (l2 > bm) { bm = l2; am = 2; }
        g_idx[t] = am;
        atomicAdd(&cnt[am], 1);
        float m = bm;
        float e0 = expf(l0 - m), e1 = expf(l1 - m), e2 = expf(l2 - m);
        float s = e0 + e1 + e2;
        atomicAdd(&proxy[0], e0/s);
        atomicAdd(&proxy[1], e1/s);
        atomicAdd(&proxy[2], e2/s);
    }
    __syncthreads();
    if (t == 0 && out_size > N_OUT) {
        float aux = 0.f;
        for (int e = 0; e < NEXP; e++)
            aux += ((float)cnt[e] / (float)B) * (proxy[e] / (float)B);
        out[N_OUT] = 0.01f * (aux * (float)NEXP);
    }
}

// =====================================================================
// Kernel 5: FUSED head conv1 3x3 (64->384) + grouped 1x1 (->2 ch per ocb) + out
// (R14 verified)
// =====================================================================
__global__ void __launch_bounds__(256)
head_fused_mma(const float* __restrict__ hb1,
               const float* __restrict__ hw2,
               const float* __restrict__ hb2,
               float* __restrict__ out)
{
    extern __shared__ char smem[];
    __shared__ float w0s[128], w1s[128], b1s[128];
    __shared__ float red0[256], red1[256];
    const uint32_t sb = smem_u32(smem);
    const int tid = threadIdx.x;
    const int wid = tid >> 5, lid = tid & 31;
    const int b   = blockIdx.z;
    const int ocb = blockIdx.y;
    const int p0  = blockIdx.x * 128;
    const int e   = g_idx[b];

    if (tid < 128) {
        w0s[tid] = hw2[(e*6 + 2*ocb)*128 + tid];
        b1s[tid] = hb1[e*384 + ocb*128 + tid];
    } else {
        w1s[tid - 128] = hw2[(e*6 + 2*ocb + 1)*128 + (tid - 128)];
    }

    const int warpM = wid >> 2, warpN = wid & 3;
    const int m0w = warpM * 64, n0w = warpN * 32;

    float acc[4][4][4];
    #pragma unroll
    for (int mt = 0; mt < 4; mt++)
        #pragma unroll
        for (int nt = 0; nt < 4; nt++)
            #pragma unroll
            for (int q = 0; q < 4; q++) acc[mt][nt][q] = 0.f;

    const int n = tid & 127;
    const int g = tid >> 7;
    const int p = p0 + n;
    const int pr = p / 96;
    const int pc = p - pr*96;
    const uint32_t* y1b = g_y1p + (size_t)b * 64 * PH*PH;

    const int rr  = lid & 7;
    const int sel = lid >> 3;

    for (int tap = 0; tap < 9; tap++) {
        const int kh = tap / 3, kw = tap - 3*(tap/3);
        __syncthreads();

        {
            const __nv_bfloat16* whb = g_wh + ((size_t)((e*9 + tap)*384 + ocb*128))*64;
            const __nv_bfloat16* wlb = g_wl + ((size_t)((e*9 + tap)*384 + ocb*128))*64;
            #pragma unroll
            for (int it = 0; it < 8; it++) {
                int idx = it*256 + tid;
                int s   = idx >> 10;
                int r   = idx & 1023;
                int oc  = r >> 3;
                int ch  = r & 7;
                const __nv_bfloat16* src = (s ? wlb : whb) + oc*64 + ch*8;
                uint4 v = *(const uint4*)src;
                *(uint4*)(smem + s*16384 + SW128((uint32_t)(oc*128 + ch*16))) = v;
            }
        }

        {
            const int ri = pr + kh - 1, ci = pc + kw - 1;
            const bool ok = ((unsigned)ri < 96u) && ((unsigned)ci < 96u);
            const uint32_t* yq = y1b + (size_t)ri*96 + ci;
            #pragma unroll
            for (int j = 0; j < 4; j++) {
                const int ic0 = g*32 + j*8;
                uint32_t pv[8];
                #pragma unroll
                for (int u = 0; u < 8; u++)
                    pv[u] = ok ? __ldg(yq + (size_t)(ic0 + u) * (PH*PH)) : 0u;
                uint32_t hp[4], lp[4];
                #pragma unroll
                for (int u = 0; u < 4; u++) {
                    hp[u] = __byte_perm(pv[2*u], pv[2*u+1], 0x5410);
                    lp[u] = __byte_perm(pv[2*u], pv[2*u+1], 0x7632);
                }
                const uint32_t off = SW128((uint32_t)(n*128 + ic0*2));
                *(uint4*)(smem + 32768 + off) = make_uint4(hp[0], hp[1], hp[2], hp[3]);
                *(uint4*)(smem + 49152 + off) = make_uint4(lp[0], lp[1], lp[2], lp[3]);
            }
        }
        __syncthreads();

        #pragma unroll
        for (int kc = 0; kc < 4; kc++) {
            const int k0b = kc*32;

            uint32_t ah[4][4], al[4][4];
            {
                const int arow = m0w + (sel & 1)*8 + rr;
                const int akb  = k0b + ((sel >> 1)*8)*2;
                #pragma unroll
                for (int mt = 0; mt < 4; mt++) {
                    uint32_t off = SW128((uint32_t)((arow + mt*16)*128 + akb));
                    LDSM4(ah[mt][0], ah[mt][1], ah[mt][2], ah[mt][3], sb + off);
                    LDSM4(al[mt][0], al[mt][1], al[mt][2], al[mt][3], sb + 16384 + off);
                }
            }

            uint32_t bh[4][2], bl[4][2];
            {
                const int brow = n0w + (sel >> 1)*8 + rr;
                const int bkb  = k0b + ((sel & 1)*8)*2;
                #pragma unroll
                for (int pair = 0; pair < 2; pair++) {
                    uint32_t off = SW128((uint32_t)((brow + pair*16)*128 + bkb));
                    LDSM4(bh[pair*2][0], bh[pair*2][1], bh[pair*2+1][0], bh[pair*2+1][1],
                          sb + 32768 + off);
                    LDSM4(bl[pair*2][0], bl[pair*2][1], bl[pair*2+1][0], bl[pair*2+1][1],
                          sb + 49152 + off);
                }
            }

            #pragma unroll
            for (int mt = 0; mt < 4; mt++)
                #pragma unroll
                for (int nt = 0; nt < 4; nt++) {
                    MMA16816(acc[mt][nt], ah[mt], bh[nt][0], bh[nt][1]);
                    MMA16816(acc[mt][nt], ah[mt], bl[nt][0], bl[nt][1]);
                    MMA16816(acc[mt][nt], al[mt], bh[nt][0], bh[nt][1]);
                }
        }
    }

    // ---- fused epilogue: acc -> epi smem [128 oc][128 px], then 1x1 conv -> out
    __syncthreads();
    float* epi = (float*)smem;
    {
        const int r  = lid >> 2;
        const int cc = (lid & 3) * 2;
        #pragma unroll
        for (int mt = 0; mt < 4; mt++)
            #pragma unroll
            for (int nt = 0; nt < 4; nt++) {
                const int m  = m0w + mt*16 + r;
                const int nn = n0w + nt*8 + cc;
                epi[m*128 + nn]         = acc[mt][nt][0];
                epi[m*128 + nn + 1]     = acc[mt][nt][1];
                epi[(m+8)*128 + nn]     = acc[mt][nt][2];
                epi[(m+8)*128 + nn + 1] = acc[mt][nt][3];
            }
    }
    __syncthreads();
    {
        const int px = tid & 127;
        const int h  = tid >> 7;
        float s0 = 0.f, s1 = 0.f;
        #pragma unroll 8
        for (int j = 0; j < 64; j++) {
            const int oc = h*64 + j;
            float v = fmaxf(epi[oc*128 + px] + b1s[oc], 0.f);
            s0 += v * w0s[oc];
            s1 += v * w1s[oc];
        }
        red0[tid] = s0;
        red1[tid] = s1;
    }
    __syncthreads();
    if (tid < 128) {
        const int px = tid;
        float o0 = hb2[e*6 + 2*ocb]     + red0[px] + red0[128 + px];
        float o1 = hb2[e*6 + 2*ocb + 1] + red1[px] + red1[128 + px];
        out[((size_t)(b*6 + 2*ocb))    *(PH*PH) + p0 + px] = o0;
        out[((size_t)(b*6 + 2*ocb + 1))*(PH*PH) + p0 + px] = o1;
    }
}

// =====================================================================
// launcher
// =====================================================================
extern "C" void kernel_launch(void* const* d_in, const int* in_sizes, int n_in,
                              void* d_out, int out_size)
{
    const float* x        = (const float*)d_in[0];
    const float* g_conv_w = (const float*)d_in[1];
    const float* g_gamma  = (const float*)d_in[2];
    const float* g_beta   = (const float*)d_in[3];
    const float* g_mean   = (const float*)d_in[4];
    const float* g_var    = (const float*)d_in[5];
    const float* g_fc_w   = (const float*)d_in[6];
    const float* g_fc_b   = (const float*)d_in[7];
    const float* e_conv1_w = (const float*)d_in[8];
    const float* e_conv1_b = (const float*)d_in[9];
    const float* e_head_w1 = (const float*)d_in[10];
    const float* e_head_b1 = (const float*)d_in[11];
    const float* e_head_w2 = (const float*)d_in[12];
    const float* e_head_b2 = (const float*)d_in[13];
    float* out = (float*)d_out;

    cudaFuncSetAttribute(head_fused_mma,
                         cudaFuncAttributeMaxDynamicSharedMemorySize, 65536);
    cudaFuncSetAttribute(gating_mma,
                         cudaFuncAttributeMaxDynamicSharedMemorySize, 32768);
    cudaFuncSetAttribute(expert_mma,
                         cudaFuncAttributeMaxDynamicSharedMemorySize, 65536);

    gw_convert<<<(49*64*16 + 255)/256, 256>>>(g_conv_w);
    ew_convert<<<(NEXP*49*64*16 + 255)/256, 256>>>(e_conv1_w);
    w_convert<<<(NEXP*384*64*9 + 255)/256, 256>>>(e_head_w1);

    dim3 ggate(GH*GH/256, B);                    // 144, 16
    gating_mma<<<ggate, 256, 32768>>>(x, g_gamma, g_beta, g_mean, g_var);

    pool_mean<<<B*64, 256>>>();

    gate_head<<<1, 64>>>(g_fc_w, g_fc_b, out, out_size);

    dim3 gexp(PH*PH/256, B);                     // 36, 16
    expert_mma<<<gexp, 256, 65536>>>(x, e_conv1_b);

    dim3 ghead(PH*PH/128, 3, B);                 // 72, 3, 16
    head_fused_mma<<<ghead, 256, 65536>>>(e_head_b1, e_head_w2, e_head_b2, out);
}

// round 16
// speedup vs baseline: 1.2531x; 1.0092x over previous
#include <cuda_runtime.h>
#include <cuda_bf16.h>
#include <cuda_fp16.h>
#include <math.h>
#include <stdint.h>

// ---------------- problem constants ----------------
#define B      16
#define CIN    15          // C*T = 3*5
#define HIN    384
#define GH     192         // gating conv out spatial
#define PH     96          // pooled / expert spatial
#define NEXP   3
#define N_OUT  (B*6*PH*PH)   // 884736

// ---------------- device scratch ----------------
__device__ float g_gate[B*64*GH*GH];
__device__ float g_feat[B*64];
__device__ int   g_idx[B];
__device__ uint32_t g_y1p[B*64*PH*PH];          // y1 packed (bf16 lo<<16 | hi), [b][ic][96][96]
__device__ __half    g_xf[B*CIN*HIN*HIN];       // x pre-converted fp16, same plane-major layout
__device__ __nv_bfloat16 g_wh[NEXP*9*384*64];   // head w1 hi [e][tap][oc][ic]
__device__ __nv_bfloat16 g_wl[NEXP*9*384*64];   // lo
__device__ __half        g_gwf[49*64*16];       // gating w fp16 [tap][oc][ic16]
__device__ __nv_bfloat16 g_ewh[NEXP*49*64*16];  // expert conv1 w hi [e][tap][oc][ic16]
__device__ __nv_bfloat16 g_ewl[NEXP*49*64*16];

// ---------------- helpers ----------------
__device__ __forceinline__ uint32_t smem_u32(const void* p) {
    uint32_t a;
    asm("{ .reg .u64 t; cvta.to.shared.u64 t, %1; cvt.u32.u64 %0, t; }" : "=r"(a) : "l"(p));
    return a;
}
#define SW128(x) ((x) ^ (((x) >> 3) & 0x70))

__device__ __forceinline__ uint32_t pkbf(__nv_bfloat16 a, __nv_bfloat16 b) {
    __nv_bfloat162 t = __halves2bfloat162(a, b);
    return *reinterpret_cast<uint32_t*>(&t);
}
__device__ __forceinline__ uint32_t pkh2(__half a, __half b) {
    __half2 t = __halves2half2(a, b);
    return *reinterpret_cast<uint32_t*>(&t);
}
// pack one fp32 value into (bf16_lo << 16) | bf16_hi
__device__ __forceinline__ uint32_t pack_split(float v) {
    __nv_bfloat16 h = __float2bfloat16_rn(v);
    __nv_bfloat16 l = __float2bfloat16_rn(v - __bfloat162float(h));
    return pkbf(h, l);
}

#define LDSM4(r0, r1, r2, r3, a) \
    asm volatile("ldmatrix.sync.aligned.m8n8.x4.shared.b16 {%0,%1,%2,%3}, [%4];" \
        : "=r"(r0), "=r"(r1), "=r"(r2), "=r"(r3) : "r"(a))

#define MMA16816(d, a, b0, b1) \
    asm volatile("mma.sync.aligned.m16n8k16.row.col.f32.bf16.bf16.f32 " \
        "{%0,%1,%2,%3}, {%4,%5,%6,%7}, {%8,%9}, {%0,%1,%2,%3};" \
        : "+f"((d)[0]), "+f"((d)[1]), "+f"((d)[2]), "+f"((d)[3]) \
        : "r"((a)[0]), "r"((a)[1]), "r"((a)[2]), "r"((a)[3]), "r"(b0), "r"(b1))

#define MMA16816F(d, a, b0, b1) \
    asm volatile("mma.sync.aligned.m16n8k16.row.col.f32.f16.f16.f32 " \
        "{%0,%1,%2,%3}, {%4,%5,%6,%7}, {%8,%9}, {%0,%1,%2,%3};" \
        : "+f"((d)[0]), "+f"((d)[1]), "+f"((d)[2]), "+f"((d)[3]) \
        : "r"((a)[0]), "r"((a)[1]), "r"((a)[2]), "r"((a)[3]), "r"(b0), "r"(b1))

// stage-area byte offsets, 48B rows (conflict-free)
#define GSA    0
#define GSB    3072
#define SA_HI 0
#define SA_LO 3072
#define SB_HI 6144
#define SB_LO 18432

// =====================================================================
// x -> fp16 plane copy (identical rounding to the old inline cvt)
// =====================================================================
__global__ void xf_convert(const float* __restrict__ x)
{
    size_t i = ((size_t)blockIdx.x * 256 + threadIdx.x) * 4;
    const size_t n = (size_t)B*CIN*HIN*HIN;
    if (i >= n) return;
    float4 v = *(const float4*)(x + i);
    __half h[4];
    h[0] = __float2half_rn(v.x);
    h[1] = __float2half_rn(v.y);
    h[2] = __float2half_rn(v.z);
    h[3] = __float2half_rn(v.w);
    *(uint2*)(g_xf + i) = make_uint2(pkh2(h[0], h[1]), pkh2(h[2], h[3]));
}

// =====================================================================
// weight convert kernels
// =====================================================================
__global__ void gw_convert(const float* __restrict__ w)   // [64][15][7][7] -> fp16
{
    int i = blockIdx.x * 256 + threadIdx.x;
    if (i >= 49*64*16) return;
    int ic = i & 15, oc = (i >> 4) & 63, tap = i >> 10;
    float v = (ic < 15) ? w[oc*735 + ic*49 + tap] : 0.f;
    g_gwf[i] = __float2half_rn(v);
}

__global__ void ew_convert(const float* __restrict__ w)   // [E][64][15][7][7]
{
    int i = blockIdx.x * 256 + threadIdx.x;
    if (i >= NEXP*49*64*16) return;
    int ic = i & 15, oc = (i >> 4) & 63, tap = (i >> 10) % 49, e = i / (49*1024);
    float v = (ic < 15) ? w[((e*64 + oc)*15 + ic)*49 + tap] : 0.f;
    __nv_bfloat16 h = __float2bfloat16_rn(v);
    __nv_bfloat16 l = __float2bfloat16_rn(v - __bfloat162float(h));
    g_ewh[i] = h;
    g_ewl[i] = l;
}

__global__ void w_convert(const float* __restrict__ w)    // head w1 [E][384][64][3][3]
{
    int i = blockIdx.x * 256 + threadIdx.x;
    if (i >= NEXP*384*64*9) return;
    int tap = i % 9;
    int r   = i / 9;
    int ic  = r % 64;
    int r2  = r / 64;
    int oc  = r2 % 384;
    int e   = r2 / 384;
    float v = w[i];
    __nv_bfloat16 h = __float2bfloat16_rn(v);
    __nv_bfloat16 l = __float2bfloat16_rn(v - __bfloat162float(h));
    int dst = ((e*9 + tap)*384 + oc)*64 + ic;
    g_wh[dst] = h;
    g_wl[dst] = l;
}

// =====================================================================
// Kernel 1: gating conv 7x7 s2 p3 (15->64) + BN + ReLU, fp16 single
// B-gather now from pre-converted fp16 planes (half L1 sector traffic)
// =====================================================================
__global__ void __launch_bounds__(256, 2)
gating_mma(const float* __restrict__ gamma,
           const float* __restrict__ beta,
           const float* __restrict__ mean,
           const float* __restrict__ var)
{
    extern __shared__ char smem[];
    const uint32_t sb = smem_u32(smem);
    const int tid = threadIdx.x;
    const int wid = tid >> 5, lid = tid & 31;
    const int b   = blockIdx.y;
    const int p0  = blockIdx.x * 256;
    const int n0w = wid * 32;

    float acc[4][4][4];
    #pragma unroll
    for (int mt = 0; mt < 4; mt++)
        #pragma unroll
        for (int nt = 0; nt < 4; nt++)
            #pragma unroll
            for (int q = 0; q < 4; q++) acc[mt][nt][q] = 0.f;

    const int p  = p0 + tid;
    const int oh = p / GH, ow = p - oh*GH;
    const int ih0 = oh*2 - 3, iw0 = ow*2 - 3;
    const __half* xb = g_xf + (size_t)b * CIN * HIN * HIN;

    const int rr = lid & 7, sel = lid >> 3;
    const int arow = tid >> 2, apart = tid & 3;
    const __half hz = __float2half_rn(0.f);

    for (int tap = 0; tap < 49; tap++) {
        const int kh = tap / 7, kw = tap - 7*(tap/7);
        __syncthreads();

        *(uint2*)(smem + GSA + arow*48 + apart*8) =
            *(const uint2*)(g_gwf + tap*1024 + arow*16 + apart*4);

        {
            const int ih = ih0 + kh, iw = iw0 + kw;
            const bool ok = ((unsigned)ih < (unsigned)HIN) && ((unsigned)iw < (unsigned)HIN);
            const __half* xq = xb + (size_t)ih*HIN + iw;
            uint32_t hp[8];
            #pragma unroll
            for (int u = 0; u < 16; u += 2) {
                __half v0 = (u < 15 && ok)     ? __ldg(xq + (size_t)u     * (HIN*HIN)) : hz;
                __half v1 = (u + 1 < 15 && ok) ? __ldg(xq + (size_t)(u+1) * (HIN*HIN)) : hz;
                hp[u >> 1] = pkh2(v0, v1);
            }
            *(uint4*)(smem + GSB + tid*48)      = make_uint4(hp[0], hp[1], hp[2], hp[3]);
            *(uint4*)(smem + GSB + tid*48 + 16) = make_uint4(hp[4], hp[5], hp[6], hp[7]);
        }
        __syncthreads();

        uint32_t ah[4][4];
        #pragma unroll
        for (int mt = 0; mt < 4; mt++) {
            const uint32_t offA = (mt*16 + (sel & 1)*8 + rr)*48 + (sel >> 1)*16;
            LDSM4(ah[mt][0], ah[mt][1], ah[mt][2], ah[mt][3], sb + GSA + offA);
        }
        uint32_t bh[4][2];
        #pragma unroll
        for (int pair = 0; pair < 2; pair++) {
            const uint32_t offB = (n0w + pair*16 + (sel >> 1)*8 + rr)*48 + (sel & 1)*16;
            LDSM4(bh[pair*2][0], bh[pair*2][1], bh[pair*2+1][0], bh[pair*2+1][1],
                  sb + GSB + offB);
        }
        #pragma unroll
        for (int mt = 0; mt < 4; mt++)
            #pragma unroll
            for (int nt = 0; nt < 4; nt++)
                MMA16816F(acc[mt][nt], ah[mt], bh[nt][0], bh[nt][1]);
    }

    // epilogue: two 32-oc chunks via smem float[32][256] (32 KB)
    float* epi = (float*)smem;
    #pragma unroll
    for (int half = 0; half < 2; half++) {
        __syncthreads();
        {
            const int r  = lid >> 2;
            const int cc = (lid & 3) * 2;
            #pragma unroll
            for (int mtl = 0; mtl < 2; mtl++) {
                const int mt = half*2 + mtl;
                #pragma unroll
                for (int nt = 0; nt < 4; nt++) {
                    const int m  = mtl*16 + r;
                    const int nn = n0w + nt*8 + cc;
                    epi[m*256 + nn]         = acc[mt][nt][0];
                    epi[m*256 + nn + 1]     = acc[mt][nt][1];
                    epi[(m+8)*256 + nn]     = acc[mt][nt][2];
                    epi[(m+8)*256 + nn + 1] = acc[mt][nt][3];
                }
            }
        }
        __syncthreads();
        #pragma unroll
        for (int it = 0; it < 8; it++) {
            int i   = it*256 + tid;
            int ocl = i >> 6;
            int oc  = half*32 + ocl;
            int cx  = (i & 63) * 4;
            float4 v = *(float4*)&epi[ocl*256 + cx];
            float inv = gamma[oc] * rsqrtf(var[oc] + 1e-5f);
            float bia = beta[oc] - mean[oc]*inv;
            v.x = fmaxf(v.x*inv + bia, 0.f);
            v.y = fmaxf(v.y*inv + bia, 0.f);
            v.z = fmaxf(v.z*inv + bia, 0.f);
            v.w = fmaxf(v.w*inv + bia, 0.f);
            *(float4*)&g_gate[((size_t)(b*64 + oc))*(GH*GH) + p0 + cx] = v;
        }
    }
}

// =====================================================================
// Kernel 4: expert conv1 7x7 s4 p3 (15->64) + bias + ReLU, bf16 split
// mainloop R5/R11 verbatim; epilogue split into two 32-oc chunks (32 KB, 2 CTA/SM)
// writes PACKED bf16 hi/lo y1
// =====================================================================
__global__ void __launch_bounds__(256, 2)
expert_mma(const float* __restrict__ x,
           const float* __restrict__ eb)
{
    extern __shared__ char smem[];
    const uint32_t sb = smem_u32(smem);
    const int tid = threadIdx.x;
    const int wid = tid >> 5, lid = tid & 31;
    const int b   = blockIdx.y;
    const int e   = g_idx[b];
    const int p0  = blockIdx.x * 256;
    const int n0w = wid * 32;

    float acc[4][4][4];
    #pragma unroll
    for (int mt = 0; mt < 4; mt++)
        #pragma unroll
        for (int nt = 0; nt < 4; nt++)
            #pragma unroll
            for (int q = 0; q < 4; q++) acc[mt][nt][q] = 0.f;

    const int p  = p0 + tid;
    const int oh = p / PH, ow = p - oh*PH;
    const int ih0 = oh*4 - 3, iw0 = ow*4 - 3;
    const float* xb = x + (size_t)b * CIN * HIN * HIN;

    const int rr = lid & 7, sel = lid >> 3;
    const int arow = tid >> 2, apart = tid & 3;
    const __nv_bfloat16* ewh = g_ewh + (size_t)e * 49*1024;
    const __nv_bfloat16* ewl = g_ewl + (size_t)e * 49*1024;

    for (int tap = 0; tap < 49; tap++) {
        const int kh = tap / 7, kw = tap - 7*(tap/7);
        __syncthreads();

        {
            const __nv_bfloat16* sh = ewh + tap*1024 + arow*16 + apart*4;
            const __nv_bfloat16* sl = ewl + tap*1024 + arow*16 + apart*4;
            *(uint2*)(smem + SA_HI + arow*48 + apart*8) = *(const uint2*)sh;
            *(uint2*)(smem + SA_LO + arow*48 + apart*8) = *(const uint2*)sl;
        }
        {
            const int ih = ih0 + kh, iw = iw0 + kw;
            const bool ok = ((unsigned)ih < (unsigned)HIN) && ((unsigned)iw < (unsigned)HIN);
            const float* xq = xb + (size_t)ih*HIN + iw;
            uint32_t hp[8], lp[8];
            #pragma unroll
            for (int u = 0; u < 16; u += 2) {
                float v0 = (u < 15 && ok)     ? __ldg(xq + (size_t)u     * (HIN*HIN)) : 0.f;
                float v1 = (u + 1 < 15 && ok) ? __ldg(xq + (size_t)(u+1) * (HIN*HIN)) : 0.f;
                __nv_bfloat16 h0 = __float2bfloat16_rn(v0);
                __nv_bfloat16 h1 = __float2bfloat16_rn(v1);
                hp[u >> 1] = pkbf(h0, h1);
                __nv_bfloat16 l0 = __float2bfloat16_rn(v0 - __bfloat162float(h0));
                __nv_bfloat16 l1 = __float2bfloat16_rn(v1 - __bfloat162float(h1));
                lp[u >> 1] = pkbf(l0, l1);
            }
            *(uint4*)(smem + SB_HI + tid*48)      = make_uint4(hp[0], hp[1], hp[2], hp[3]);
            *(uint4*)(smem + SB_HI + tid*48 + 16) = make_uint4(hp[4], hp[5], hp[6], hp[7]);
            *(uint4*)(smem + SB_LO + tid*48)      = make_uint4(lp[0], lp[1], lp[2], lp[3]);
            *(uint4*)(smem + SB_LO + tid*48 + 16) = make_uint4(lp[4], lp[5], lp[6], lp[7]);
        }
        __syncthreads();

        uint32_t ah[4][4], al[4][4];
        #pragma unroll
        for (int mt = 0; mt < 4; mt++) {
            const uint32_t offA = (mt*16 + (sel & 1)*8 + rr)*48 + (sel >> 1)*16;
            LDSM4(ah[mt][0], ah[mt][1], ah[mt][2], ah[mt][3], sb + SA_HI + offA);
            LDSM4(al[mt][0], al[mt][1], al[mt][2], al[mt][3], sb + SA_LO + offA);
        }
        uint32_t bh[4][2], bl[4][2];
        #pragma unroll
        for (int pair = 0; pair < 2; pair++) {
            const uint32_t offB = (n0w + pair*16 + (sel >> 1)*8 + rr)*48 + (sel & 1)*16;
            LDSM4(bh[pair*2][0], bh[pair*2][1], bh[pair*2+1][0], bh[pair*2+1][1],
                  sb + SB_HI + offB);
            LDSM4(bl[pair*2][0], bl[pair*2][1], bl[pair*2+1][0], bl[pair*2+1][1],
                  sb + SB_LO + offB);
        }
        #pragma unroll
        for (int mt = 0; mt < 4; mt++)
            #pragma unroll
            for (int nt = 0; nt < 4; nt++) {
                MMA16816(acc[mt][nt], ah[mt], bh[nt][0], bh[nt][1]);
                MMA16816(acc[mt][nt], ah[mt], bl[nt][0], bl[nt][1]);
                MMA16816(acc[mt][nt], al[mt], bh[nt][0], bh[nt][1]);
            }
    }

    // epilogue: two 32-oc chunks via smem float[32][256] (32 KB)
    float* epi = (float*)smem;
    const float* bb = eb + e*64;
    #pragma unroll
    for (int half = 0; half < 2; half++) {
        __syncthreads();
        {
            const int r  = lid >> 2;
            const int cc = (lid & 3) * 2;
            #pragma unroll
            for (int mtl = 0; mtl < 2; mtl++) {
                const int mt = half*2 + mtl;
                #pragma unroll
                for (int nt = 0; nt < 4; nt++) {
                    const int m  = mtl*16 + r;
                    const int nn = n0w + nt*8 + cc;
                    epi[m*256 + nn]         = acc[mt][nt][0];
                    epi[m*256 + nn + 1]     = acc[mt][nt][1];
                    epi[(m+8)*256 + nn]     = acc[mt][nt][2];
                    epi[(m+8)*256 + nn + 1] = acc[mt][nt][3];
                }
            }
        }
        __syncthreads();
        #pragma unroll
        for (int it = 0; it < 8; it++) {
            int i   = it*256 + tid;
            int ocl = i >> 6;
            int oc  = half*32 + ocl;
            int cx  = (i & 63) * 4;
            float4 v = *(float4*)&epi[ocl*256 + cx];
            float bias = bb[oc];
            v.x = fmaxf(v.x + bias, 0.f);
            v.y = fmaxf(v.y + bias, 0.f);
            v.z = fmaxf(v.z + bias, 0.f);
            v.w = fmaxf(v.w + bias, 0.f);
            uint4 pk;
            pk.x = pack_split(v.x);
            pk.y = pack_split(v.y);
            pk.z = pack_split(v.z);
            pk.w = pack_split(v.w);
            *(uint4*)&g_y1p[((size_t)(b*64 + oc))*(PH*PH) + p0 + cx] = pk;
        }
    }
}

// =====================================================================
// Kernel 2: maxpool 3x3 s2 p1 + spatial mean
// =====================================================================
__global__ void pool_mean()
{
    const int bc = blockIdx.x;
    const float* src = g_gate + (size_t)bc * GH * GH;
    const int tid = threadIdx.x;
    float sum = 0.f;
    for (int p = tid; p < PH*PH; p += 256) {
        int ph = p / PH, pw = p - ph*PH;
        float m = -1e30f;
        #pragma unroll
        for (int r = 0; r < 3; r++) {
            int ih = 2*ph - 1 + r;
            if ((unsigned)ih >= (unsigned)GH) continue;
            #pragma unroll
            for (int c = 0; c < 3; c++) {
                int iw = 2*pw - 1 + c;
                if ((unsigned)iw >= (unsigned)GH) continue;
                m = fmaxf(m, src[ih*GH + iw]);
            }
        }
        sum += m;
    }
    __shared__ float red[256];
    red[tid] = sum;
    __syncthreads();
    for (int s = 128; s > 0; s >>= 1) {
        if (tid < s) red[tid] += red[tid + s];
        __syncthreads();
    }
    if (tid == 0) g_feat[bc] = red[0] / (float)(PH*PH);
}

// =====================================================================
// Kernel 3: logits, argmax, aux loss
// =====================================================================
__global__ void gate_head(const float* __restrict__ fcw,
                          const float* __restrict__ fcb,
                          float* __restrict__ out, int out_size)
{
    __shared__ float lg[B][NEXP];
    __shared__ float proxy[NEXP];
    __shared__ int   cnt[NEXP];
    const int t = threadIdx.x;

    if (t < NEXP) { proxy[t] = 0.f; cnt[t] = 0; }
    if (t < B*NEXP) {
        int b = t / NEXP, e = t - b*NEXP;
        float s = fcb[e];
        const float* f = g_feat + b*64;
        const float* wr = fcw + e*64;
        for (int c = 0; c < 64; c++) s += f[c]*wr[c];
        lg[b][e] = s;
    }
    __syncthreads();
    if (t < B) {
        float l0 = lg[t][0], l1 = lg[t][1], l2 = lg[t][2];
        int am = 0; float bm = l0;
        if (l1 > bm) { bm = l1; am = 1; }
        if (l2 > bm) { bm = l2; am = 2; }
        g_idx[t] = am;
        atomicAdd(&cnt[am], 1);
        float m = bm;
        float e0 = expf(l0 - m), e1 = expf(l1 - m), e2 = expf(l2 - m);
        float s = e0 + e1 + e2;
        atomicAdd(&proxy[0], e0/s);
        atomicAdd(&proxy[1], e1/s);
        atomicAdd(&proxy[2], e2/s);
    }
    __syncthreads();
    if (t == 0 && out_size > N_OUT) {
        float aux = 0.f;
        for (int e = 0; e < NEXP; e++)
            aux += ((float)cnt[e] / (float)B) * (proxy[e] / (float)B);
        out[N_OUT] = 0.01f * (aux * (float)NEXP);
    }
}

// =====================================================================
// Kernel 5: FUSED head conv1 3x3 (64->384) + grouped 1x1 (->2 ch per ocb) + out
// (R14 verified)
// =====================================================================
__global__ void __launch_bounds__(256)
head_fused_mma(const float* __restrict__ hb1,
               const float* __restrict__ hw2,
               const float* __restrict__ hb2,
               float* __restrict__ out)
{
    extern __shared__ char smem[];
    __shared__ float w0s[128], w1s[128], b1s[128];
    __shared__ float red0[256], red1[256];
    const uint32_t sb = smem_u32(smem);
    const int tid = threadIdx.x;
    const int wid = tid >> 5, lid = tid & 31;
    const int b   = blockIdx.z;
    const int ocb = blockIdx.y;
    const int p0  = blockIdx.x * 128;
    const int e   = g_idx[b];

    if (tid < 128) {
        w0s[tid] = hw2[(e*6 + 2*ocb)*128 + tid];
        b1s[tid] = hb1[e*384 + ocb*128 + tid];
    } else {
        w1s[tid - 128] = hw2[(e*6 + 2*ocb + 1)*128 + (tid - 128)];
    }

    const int warpM = wid >> 2, warpN = wid & 3;
    const int m0w = warpM * 64, n0w = warpN * 32;

    float acc[4][4][4];
    #pragma unroll
    for (int mt = 0; mt < 4; mt++)
        #pragma unroll
        for (int nt = 0; nt < 4; nt++)
            #pragma unroll
            for (int q = 0; q < 4; q++) acc[mt][nt][q] = 0.f;

    const int n = tid & 127;
    const int g = tid >> 7;
    const int p = p0 + n;
    const int pr = p / 96;
    const int pc = p - pr*96;
    const uint32_t* y1b = g_y1p + (size_t)b * 64 * PH*PH;

    const int rr  = lid & 7;
    const int sel = lid >> 3;

    for (int tap = 0; tap < 9; tap++) {
        const int kh = tap / 3, kw = tap - 3*(tap/3);
        __syncthreads();

        {
            const __nv_bfloat16* whb = g_wh + ((size_t)((e*9 + tap)*384 + ocb*128))*64;
            const __nv_bfloat16* wlb = g_wl + ((size_t)((e*9 + tap)*384 + ocb*128))*64;
            #pragma unroll
            for (int it = 0; it < 8; it++) {
                int idx = it*256 + tid;
                int s   = idx >> 10;
                int r   = idx & 1023;
                int oc  = r >> 3;
                int ch  = r & 7;
                const __nv_bfloat16* src = (s ? wlb : whb) + oc*64 + ch*8;
                uint4 v = *(const uint4*)src;
                *(uint4*)(smem + s*16384 + SW128((uint32_t)(oc*128 + ch*16))) = v;
            }
        }

        {
            const int ri = pr + kh - 1, ci = pc + kw - 1;
            const bool ok = ((unsigned)ri < 96u) && ((unsigned)ci < 96u);
            const uint32_t* yq = y1b + (size_t)ri*96 + ci;
            #pragma unroll
            for (int j = 0; j < 4; j++) {
                const int ic0 = g*32 + j*8;
                uint32_t pv[8];
                #pragma unroll
                for (int u = 0; u < 8; u++)
                    pv[u] = ok ? __ldg(yq + (size_t)(ic0 + u) * (PH*PH)) : 0u;
                uint32_t hp[4], lp[4];
                #pragma unroll
                for (int u = 0; u < 4; u++) {
                    hp[u] = __byte_perm(pv[2*u], pv[2*u+1], 0x5410);
                    lp[u] = __byte_perm(pv[2*u], pv[2*u+1], 0x7632);
                }
                const uint32_t off = SW128((uint32_t)(n*128 + ic0*2));
                *(uint4*)(smem + 32768 + off) = make_uint4(hp[0], hp[1], hp[2], hp[3]);
                *(uint4*)(smem + 49152 + off) = make_uint4(lp[0], lp[1], lp[2], lp[3]);
            }
        }
        __syncthreads();

        #pragma unroll
        for (int kc = 0; kc < 4; kc++) {
            const int k0b = kc*32;

            uint32_t ah[4][4], al[4][4];
            {
                const int arow = m0w + (sel & 1)*8 + rr;
                const int akb  = k0b + ((sel >> 1)*8)*2;
                #pragma unroll
                for (int mt = 0; mt < 4; mt++) {
                    uint32_t off = SW128((uint32_t)((arow + mt*16)*128 + akb));
                    LDSM4(ah[mt][0], ah[mt][1], ah[mt][2], ah[mt][3], sb + off);
                    LDSM4(al[mt][0], al[mt][1], al[mt][2], al[mt][3], sb + 16384 + off);
                }
            }

            uint32_t bh[4][2], bl[4][2];
            {
                const int brow = n0w + (sel >> 1)*8 + rr;
                const int bkb  = k0b + ((sel & 1)*8)*2;
                #pragma unroll
                for (int pair = 0; pair < 2; pair++) {
                    uint32_t off = SW128((uint32_t)((brow + pair*16)*128 + bkb));
                    LDSM4(bh[pair*2][0], bh[pair*2][1], bh[pair*2+1][0], bh[pair*2+1][1],
                          sb + 32768 + off);
                    LDSM4(bl[pair*2][0], bl[pair*2][1], bl[pair*2+1][0], bl[pair*2+1][1],
                          sb + 49152 + off);
                }
            }

            #pragma unroll
            for (int mt = 0; mt < 4; mt++)
                #pragma unroll
                for (int nt = 0; nt < 4; nt++) {
                    MMA16816(acc[mt][nt], ah[mt], bh[nt][0], bh[nt][1]);
                    MMA16816(acc[mt][nt], ah[mt], bl[nt][0], bl[nt][1]);
                    MMA16816(acc[mt][nt], al[mt], bh[nt][0], bh[nt][1]);
                }
        }
    }

    // ---- fused epilogue: acc -> epi smem [128 oc][128 px], then 1x1 conv -> out
    __syncthreads();
    float* epi = (float*)smem;
    {
        const int r  = lid >> 2;
        const int cc = (lid & 3) * 2;
        #pragma unroll
        for (int mt = 0; mt < 4; mt++)
            #pragma unroll
            for (int nt = 0; nt < 4; nt++) {
                const int m  = m0w + mt*16 + r;
                const int nn = n0w + nt*8 + cc;
                epi[m*128 + nn]         = acc[mt][nt][0];
                epi[m*128 + nn + 1]     = acc[mt][nt][1];
                epi[(m+8)*128 + nn]     = acc[mt][nt][2];
                epi[(m+8)*128 + nn + 1] = acc[mt][nt][3];
            }
    }
    __syncthreads();
    {
        const int px = tid & 127;
        const int h  = tid >> 7;
        float s0 = 0.f, s1 = 0.f;
        #pragma unroll 8
        for (int j = 0; j < 64; j++) {
            const int oc = h*64 + j;
            float v = fmaxf(epi[oc*128 + px] + b1s[oc], 0.f);
            s0 += v * w0s[oc];
            s1 += v * w1s[oc];
        }
        red0[tid] = s0;
        red1[tid] = s1;
    }
    __syncthreads();
    if (tid < 128) {
        const int px = tid;
        float o0 = hb2[e*6 + 2*ocb]     + red0[px] + red0[128 + px];
        float o1 = hb2[e*6 + 2*ocb + 1] + red1[px] + red1[128 + px];
        out[((size_t)(b*6 + 2*ocb))    *(PH*PH) + p0 + px] = o0;
        out[((size_t)(b*6 + 2*ocb + 1))*(PH*PH) + p0 + px] = o1;
    }
}

// =====================================================================
// launcher
// =====================================================================
extern "C" void kernel_launch(void* const* d_in, const int* in_sizes, int n_in,
                              void* d_out, int out_size)
{
    const float* x        = (const float*)d_in[0];
    const float* g_conv_w = (const float*)d_in[1];
    const float* g_gamma  = (const float*)d_in[2];
    const float* g_beta   = (const float*)d_in[3];
    const float* g_mean   = (const float*)d_in[4];
    const float* g_var    = (const float*)d_in[5];
    const float* g_fc_w   = (const float*)d_in[6];
    const float* g_fc_b   = (const float*)d_in[7];
    const float* e_conv1_w = (const float*)d_in[8];
    const float* e_conv1_b = (const float*)d_in[9];
    const float* e_head_w1 = (const float*)d_in[10];
    const float* e_head_b1 = (const float*)d_in[11];
    const float* e_head_w2 = (const float*)d_in[12];
    const float* e_head_b2 = (const float*)d_in[13];
    float* out = (float*)d_out;

    cudaFuncSetAttribute(head_fused_mma,
                         cudaFuncAttributeMaxDynamicSharedMemorySize, 65536);
    cudaFuncSetAttribute(gating_mma,
                         cudaFuncAttributeMaxDynamicSharedMemorySize, 32768);
    cudaFuncSetAttribute(expert_mma,
                         cudaFuncAttributeMaxDynamicSharedMemorySize, 32768);

    gw_convert<<<(49*64*16 + 255)/256, 256>>>(g_conv_w);
    ew_convert<<<(NEXP*49*64*16 + 255)/256, 256>>>(e_conv1_w);
    w_convert<<<(NEXP*384*64*9 + 255)/256, 256>>>(e_head_w1);

    size_t nx = (size_t)B*CIN*HIN*HIN;
    xf_convert<<<(unsigned)((nx/4 + 255)/256), 256>>>(x);

    dim3 ggate(GH*GH/256, B);                    // 144, 16
    gating_mma<<<ggate, 256, 32768>>>(g_gamma, g_beta, g_mean, g_var);

    pool_mean<<<B*64, 256>>>();

    gate_head<<<1, 64>>>(g_fc_w, g_fc_b, out, out_size);

    dim3 gexp(PH*PH/256, B);                     // 36, 16
    expert_mma<<<gexp, 256, 32768>>>(x, e_conv1_b);

    dim3 ghead(PH*PH/128, 3, B);                 // 72, 3, 16
    head_fused_mma<<<ghead, 256, 65536>>>(e_head_b1, e_head_w2, e_head_b2, out);
}

// round 17
// speedup vs baseline: 1.3424x; 1.0712x over previous
#include <cuda_runtime.h>
#include <cuda_bf16.h>
#include <cuda_fp16.h>
#include <math.h>
#include <stdint.h>

// ---------------- problem constants ----------------
#define B      16
#define CIN    15          // C*T = 3*5
#define HIN    384
#define GH     192         // gating conv out spatial
#define PH     96          // pooled / expert spatial
#define NEXP   3
#define N_OUT  (B*6*PH*PH)   // 884736

// ---------------- device scratch ----------------
__device__ float g_gate[B*64*GH*GH];
__device__ float g_feat[B*64];
__device__ int   g_idx[B];
__device__ uint32_t g_y1p[B*64*PH*PH];          // y1 packed (bf16 lo<<16 | hi), [b][ic][96][96]
__device__ __half    g_xf[B*CIN*HIN*HIN];       // x pre-converted fp16, plane-major
__device__ __nv_bfloat16 g_wh[NEXP*9*384*64];   // head w1 hi [e][tap][oc][ic]
__device__ __nv_bfloat16 g_wl[NEXP*9*384*64];   // lo
__device__ __half        g_gwf[49*64*16];       // gating w fp16 [tap][oc][ic16]
__device__ __half        g_ewf[NEXP*49*64*16];  // expert conv1 w fp16 [e][tap][oc][ic16]

// ---------------- helpers ----------------
__device__ __forceinline__ uint32_t smem_u32(const void* p) {
    uint32_t a;
    asm("{ .reg .u64 t; cvta.to.shared.u64 t, %1; cvt.u32.u64 %0, t; }" : "=r"(a) : "l"(p));
    return a;
}
#define SW128(x) ((x) ^ (((x) >> 3) & 0x70))

__device__ __forceinline__ uint32_t pkbf(__nv_bfloat16 a, __nv_bfloat16 b) {
    __nv_bfloat162 t = __halves2bfloat162(a, b);
    return *reinterpret_cast<uint32_t*>(&t);
}
__device__ __forceinline__ uint32_t pkh2(__half a, __half b) {
    __half2 t = __halves2half2(a, b);
    return *reinterpret_cast<uint32_t*>(&t);
}
// pack one fp32 value into (bf16_lo << 16) | bf16_hi
__device__ __forceinline__ uint32_t pack_split(float v) {
    __nv_bfloat16 h = __float2bfloat16_rn(v);
    __nv_bfloat16 l = __float2bfloat16_rn(v - __bfloat162float(h));
    return pkbf(h, l);
}

#define LDSM4(r0, r1, r2, r3, a) \
    asm volatile("ldmatrix.sync.aligned.m8n8.x4.shared.b16 {%0,%1,%2,%3}, [%4];" \
        : "=r"(r0), "=r"(r1), "=r"(r2), "=r"(r3) : "r"(a))

#define MMA16816(d, a, b0, b1) \
    asm volatile("mma.sync.aligned.m16n8k16.row.col.f32.bf16.bf16.f32 " \
        "{%0,%1,%2,%3}, {%4,%5,%6,%7}, {%8,%9}, {%0,%1,%2,%3};" \
        : "+f"((d)[0]), "+f"((d)[1]), "+f"((d)[2]), "+f"((d)[3]) \
        : "r"((a)[0]), "r"((a)[1]), "r"((a)[2]), "r"((a)[3]), "r"(b0), "r"(b1))

#define MMA16816F(d, a, b0, b1) \
    asm volatile("mma.sync.aligned.m16n8k16.row.col.f32.f16.f16.f32 " \
        "{%0,%1,%2,%3}, {%4,%5,%6,%7}, {%8,%9}, {%0,%1,%2,%3};" \
        : "+f"((d)[0]), "+f"((d)[1]), "+f"((d)[2]), "+f"((d)[3]) \
        : "r"((a)[0]), "r"((a)[1]), "r"((a)[2]), "r"((a)[3]), "r"(b0), "r"(b1))

// stage-area byte offsets, 48B rows (conflict-free)
#define GSA    0
#define GSB    3072

// =====================================================================
// x -> fp16 plane copy
// =====================================================================
__global__ void xf_convert(const float* __restrict__ x)
{
    size_t i = ((size_t)blockIdx.x * 256 + threadIdx.x) * 4;
    const size_t n = (size_t)B*CIN*HIN*HIN;
    if (i >= n) return;
    float4 v = *(const float4*)(x + i);
    __half h[4];
    h[0] = __float2half_rn(v.x);
    h[1] = __float2half_rn(v.y);
    h[2] = __float2half_rn(v.z);
    h[3] = __float2half_rn(v.w);
    *(uint2*)(g_xf + i) = make_uint2(pkh2(h[0], h[1]), pkh2(h[2], h[3]));
}

// =====================================================================
// weight convert kernels
// =====================================================================
__global__ void gw_convert(const float* __restrict__ w)   // [64][15][7][7] -> fp16
{
    int i = blockIdx.x * 256 + threadIdx.x;
    if (i >= 49*64*16) return;
    int ic = i & 15, oc = (i >> 4) & 63, tap = i >> 10;
    float v = (ic < 15) ? w[oc*735 + ic*49 + tap] : 0.f;
    g_gwf[i] = __float2half_rn(v);
}

__global__ void ew_convert(const float* __restrict__ w)   // [E][64][15][7][7] -> fp16
{
    int i = blockIdx.x * 256 + threadIdx.x;
    if (i >= NEXP*49*64*16) return;
    int ic = i & 15, oc = (i >> 4) & 63, tap = (i >> 10) % 49, e = i / (49*1024);
    float v = (ic < 15) ? w[((e*64 + oc)*15 + ic)*49 + tap] : 0.f;
    g_ewf[i] = __float2half_rn(v);
}

__global__ void w_convert(const float* __restrict__ w)    // head w1 [E][384][64][3][3]
{
    int i = blockIdx.x * 256 + threadIdx.x;
    if (i >= NEXP*384*64*9) return;
    int tap = i % 9;
    int r   = i / 9;
    int ic  = r % 64;
    int r2  = r / 64;
    int oc  = r2 % 384;
    int e   = r2 / 384;
    float v = w[i];
    __nv_bfloat16 h = __float2bfloat16_rn(v);
    __nv_bfloat16 l = __float2bfloat16_rn(v - __bfloat162float(h));
    int dst = ((e*9 + tap)*384 + oc)*64 + ic;
    g_wh[dst] = h;
    g_wl[dst] = l;
}

// =====================================================================
// Kernel 1: gating conv 7x7 s2 p3 (15->64) + BN + ReLU, fp16 single (R16 verified)
// =====================================================================
__global__ void __launch_bounds__(256, 2)
gating_mma(const float* __restrict__ gamma,
           const float* __restrict__ beta,
           const float* __restrict__ mean,
           const float* __restrict__ var)
{
    extern __shared__ char smem[];
    const uint32_t sb = smem_u32(smem);
    const int tid = threadIdx.x;
    const int wid = tid >> 5, lid = tid & 31;
    const int b   = blockIdx.y;
    const int p0  = blockIdx.x * 256;
    const int n0w = wid * 32;

    float acc[4][4][4];
    #pragma unroll
    for (int mt = 0; mt < 4; mt++)
        #pragma unroll
        for (int nt = 0; nt < 4; nt++)
            #pragma unroll
            for (int q = 0; q < 4; q++) acc[mt][nt][q] = 0.f;

    const int p  = p0 + tid;
    const int oh = p / GH, ow = p - oh*GH;
    const int ih0 = oh*2 - 3, iw0 = ow*2 - 3;
    const __half* xb = g_xf + (size_t)b * CIN * HIN * HIN;

    const int rr = lid & 7, sel = lid >> 3;
    const int arow = tid >> 2, apart = tid & 3;
    const __half hz = __float2half_rn(0.f);

    for (int tap = 0; tap < 49; tap++) {
        const int kh = tap / 7, kw = tap - 7*(tap/7);
        __syncthreads();

        *(uint2*)(smem + GSA + arow*48 + apart*8) =
            *(const uint2*)(g_gwf + tap*1024 + arow*16 + apart*4);

        {
            const int ih = ih0 + kh, iw = iw0 + kw;
            const bool ok = ((unsigned)ih < (unsigned)HIN) && ((unsigned)iw < (unsigned)HIN);
            const __half* xq = xb + (size_t)ih*HIN + iw;
            uint32_t hp[8];
            #pragma unroll
            for (int u = 0; u < 16; u += 2) {
                __half v0 = (u < 15 && ok)     ? __ldg(xq + (size_t)u     * (HIN*HIN)) : hz;
                __half v1 = (u + 1 < 15 && ok) ? __ldg(xq + (size_t)(u+1) * (HIN*HIN)) : hz;
                hp[u >> 1] = pkh2(v0, v1);
            }
            *(uint4*)(smem + GSB + tid*48)      = make_uint4(hp[0], hp[1], hp[2], hp[3]);
            *(uint4*)(smem + GSB + tid*48 + 16) = make_uint4(hp[4], hp[5], hp[6], hp[7]);
        }
        __syncthreads();

        uint32_t ah[4][4];
        #pragma unroll
        for (int mt = 0; mt < 4; mt++) {
            const uint32_t offA = (mt*16 + (sel & 1)*8 + rr)*48 + (sel >> 1)*16;
            LDSM4(ah[mt][0], ah[mt][1], ah[mt][2], ah[mt][3], sb + GSA + offA);
        }
        uint32_t bh[4][2];
        #pragma unroll
        for (int pair = 0; pair < 2; pair++) {
            const uint32_t offB = (n0w + pair*16 + (sel >> 1)*8 + rr)*48 + (sel & 1)*16;
            LDSM4(bh[pair*2][0], bh[pair*2][1], bh[pair*2+1][0], bh[pair*2+1][1],
                  sb + GSB + offB);
        }
        #pragma unroll
        for (int mt = 0; mt < 4; mt++)
            #pragma unroll
            for (int nt = 0; nt < 4; nt++)
                MMA16816F(acc[mt][nt], ah[mt], bh[nt][0], bh[nt][1]);
    }

    // epilogue: two 32-oc chunks via smem float[32][256] (32 KB)
    float* epi = (float*)smem;
    #pragma unroll
    for (int half = 0; half < 2; half++) {
        __syncthreads();
        {
            const int r  = lid >> 2;
            const int cc = (lid & 3) * 2;
            #pragma unroll
            for (int mtl = 0; mtl < 2; mtl++) {
                const int mt = half*2 + mtl;
                #pragma unroll
                for (int nt = 0; nt < 4; nt++) {
                    const int m  = mtl*16 + r;
                    const int nn = n0w + nt*8 + cc;
                    epi[m*256 + nn]         = acc[mt][nt][0];
                    epi[m*256 + nn + 1]     = acc[mt][nt][1];
                    epi[(m+8)*256 + nn]     = acc[mt][nt][2];
                    epi[(m+8)*256 + nn + 1] = acc[mt][nt][3];
                }
            }
        }
        __syncthreads();
        #pragma unroll
        for (int it = 0; it < 8; it++) {
            int i   = it*256 + tid;
            int ocl = i >> 6;
            int oc  = half*32 + ocl;
            int cx  = (i & 63) * 4;
            float4 v = *(float4*)&epi[ocl*256 + cx];
            float inv = gamma[oc] * rsqrtf(var[oc] + 1e-5f);
            float bia = beta[oc] - mean[oc]*inv;
            v.x = fmaxf(v.x*inv + bia, 0.f);
            v.y = fmaxf(v.y*inv + bia, 0.f);
            v.z = fmaxf(v.z*inv + bia, 0.f);
            v.w = fmaxf(v.w*inv + bia, 0.f);
            *(float4*)&g_gate[((size_t)(b*64 + oc))*(GH*GH) + p0 + cx] = v;
        }
    }
}

// =====================================================================
// Kernel 4: expert conv1 7x7 s4 p3 (15->64) + bias + ReLU, fp16 single MMA
// (same structure as gating_mma; bias epilogue; writes packed y1p)
// =====================================================================
__global__ void __launch_bounds__(256, 2)
expert_mma(const float* __restrict__ eb)
{
    extern __shared__ char smem[];
    const uint32_t sb = smem_u32(smem);
    const int tid = threadIdx.x;
    const int wid = tid >> 5, lid = tid & 31;
    const int b   = blockIdx.y;
    const int e   = g_idx[b];
    const int p0  = blockIdx.x * 256;
    const int n0w = wid * 32;

    float acc[4][4][4];
    #pragma unroll
    for (int mt = 0; mt < 4; mt++)
        #pragma unroll
        for (int nt = 0; nt < 4; nt++)
            #pragma unroll
            for (int q = 0; q < 4; q++) acc[mt][nt][q] = 0.f;

    const int p  = p0 + tid;
    const int oh = p / PH, ow = p - oh*PH;
    const int ih0 = oh*4 - 3, iw0 = ow*4 - 3;
    const __half* xb = g_xf + (size_t)b * CIN * HIN * HIN;

    const int rr = lid & 7, sel = lid >> 3;
    const int arow = tid >> 2, apart = tid & 3;
    const __half* ewf = g_ewf + (size_t)e * 49*1024;
    const __half hz = __float2half_rn(0.f);

    for (int tap = 0; tap < 49; tap++) {
        const int kh = tap / 7, kw = tap - 7*(tap/7);
        __syncthreads();

        *(uint2*)(smem + GSA + arow*48 + apart*8) =
            *(const uint2*)(ewf + tap*1024 + arow*16 + apart*4);

        {
            const int ih = ih0 + kh, iw = iw0 + kw;
            const bool ok = ((unsigned)ih < (unsigned)HIN) && ((unsigned)iw < (unsigned)HIN);
            const __half* xq = xb + (size_t)ih*HIN + iw;
            uint32_t hp[8];
            #pragma unroll
            for (int u = 0; u < 16; u += 2) {
                __half v0 = (u < 15 && ok)     ? __ldg(xq + (size_t)u     * (HIN*HIN)) : hz;
                __half v1 = (u + 1 < 15 && ok) ? __ldg(xq + (size_t)(u+1) * (HIN*HIN)) : hz;
                hp[u >> 1] = pkh2(v0, v1);
            }
            *(uint4*)(smem + GSB + tid*48)      = make_uint4(hp[0], hp[1], hp[2], hp[3]);
            *(uint4*)(smem + GSB + tid*48 + 16) = make_uint4(hp[4], hp[5], hp[6], hp[7]);
        }
        __syncthreads();

        uint32_t ah[4][4];
        #pragma unroll
        for (int mt = 0; mt < 4; mt++) {
            const uint32_t offA = (mt*16 + (sel & 1)*8 + rr)*48 + (sel >> 1)*16;
            LDSM4(ah[mt][0], ah[mt][1], ah[mt][2], ah[mt][3], sb + GSA + offA);
        }
        uint32_t bh[4][2];
        #pragma unroll
        for (int pair = 0; pair < 2; pair++) {
            const uint32_t offB = (n0w + pair*16 + (sel >> 1)*8 + rr)*48 + (sel & 1)*16;
            LDSM4(bh[pair*2][0], bh[pair*2][1], bh[pair*2+1][0], bh[pair*2+1][1],
                  sb + GSB + offB);
        }
        #pragma unroll
        for (int mt = 0; mt < 4; mt++)
            #pragma unroll
            for (int nt = 0; nt < 4; nt++)
                MMA16816F(acc[mt][nt], ah[mt], bh[nt][0], bh[nt][1]);
    }

    // epilogue: two 32-oc chunks; bias+ReLU; write packed bf16 hi/lo y1
    float* epi = (float*)smem;
    const float* bb = eb + e*64;
    #pragma unroll
    for (int half = 0; half < 2; half++) {
        __syncthreads();
        {
            const int r  = lid >> 2;
            const int cc = (lid & 3) * 2;
            #pragma unroll
            for (int mtl = 0; mtl < 2; mtl++) {
                const int mt = half*2 + mtl;
                #pragma unroll
                for (int nt = 0; nt < 4; nt++) {
                    const int m  = mtl*16 + r;
                    const int nn = n0w + nt*8 + cc;
                    epi[m*256 + nn]         = acc[mt][nt][0];
                    epi[m*256 + nn + 1]     = acc[mt][nt][1];
                    epi[(m+8)*256 + nn]     = acc[mt][nt][2];
                    epi[(m+8)*256 + nn + 1] = acc[mt][nt][3];
                }
            }
        }
        __syncthreads();
        #pragma unroll
        for (int it = 0; it < 8; it++) {
            int i   = it*256 + tid;
            int ocl = i >> 6;
            int oc  = half*32 + ocl;
            int cx  = (i & 63) * 4;
            float4 v = *(float4*)&epi[ocl*256 + cx];
            float bias = bb[oc];
            v.x = fmaxf(v.x + bias, 0.f);
            v.y = fmaxf(v.y + bias, 0.f);
            v.z = fmaxf(v.z + bias, 0.f);
            v.w = fmaxf(v.w + bias, 0.f);
            uint4 pk;
            pk.x = pack_split(v.x);
            pk.y = pack_split(v.y);
            pk.z = pack_split(v.z);
            pk.w = pack_split(v.w);
            *(uint4*)&g_y1p[((size_t)(b*64 + oc))*(PH*PH) + p0 + cx] = pk;
        }
    }
}

// =====================================================================
// Kernel 2: maxpool 3x3 s2 p1 + spatial mean
// =====================================================================
__global__ void pool_mean()
{
    const int bc = blockIdx.x;
    const float* src = g_gate + (size_t)bc * GH * GH;
    const int tid = threadIdx.x;
    float sum = 0.f;
    for (int p = tid; p < PH*PH; p += 256) {
        int ph = p / PH, pw = p - ph*PH;
        float m = -1e30f;
        #pragma unroll
        for (int r = 0; r < 3; r++) {
            int ih = 2*ph - 1 + r;
            if ((unsigned)ih >= (unsigned)GH) continue;
            #pragma unroll
            for (int c = 0; c < 3; c++) {
                int iw = 2*pw - 1 + c;
                if ((unsigned)iw >= (unsigned)GH) continue;
                m = fmaxf(m, src[ih*GH + iw]);
            }
        }
        sum += m;
    }
    __shared__ float red[256];
    red[tid] = sum;
    __syncthreads();
    for (int s = 128; s > 0; s >>= 1) {
        if (tid < s) red[tid] += red[tid + s];
        __syncthreads();
    }
    if (tid == 0) g_feat[bc] = red[0] / (float)(PH*PH);
}

// =====================================================================
// Kernel 3: logits, argmax, aux loss
// =====================================================================
__global__ void gate_head(const float* __restrict__ fcw,
                          const float* __restrict__ fcb,
                          float* __restrict__ out, int out_size)
{
    __shared__ float lg[B][NEXP];
    __shared__ float proxy[NEXP];
    __shared__ int   cnt[NEXP];
    const int t = threadIdx.x;

    if (t < NEXP) { proxy[t] = 0.f; cnt[t] = 0; }
    if (t < B*NEXP) {
        int b = t / NEXP, e = t - b*NEXP;
        float s = fcb[e];
        const float* f = g_feat + b*64;
        const float* wr = fcw + e*64;
        for (int c = 0; c < 64; c++) s += f[c]*wr[c];
        lg[b][e] = s;
    }
    __syncthreads();
    if (t < B) {
        float l0 = lg[t][0], l1 = lg[t][1], l2 = lg[t][2];
        int am = 0; float bm = l0;
        if (l1 > bm) { bm = l1; am = 1; }
        if (l2 > bm) { bm = l2; am = 2; }
        g_idx[t] = am;
        atomicAdd(&cnt[am], 1);
        float m = bm;
        float e0 = expf(l0 - m), e1 = expf(l1 - m), e2 = expf(l2 - m);
        float s = e0 + e1 + e2;
        atomicAdd(&proxy[0], e0/s);
        atomicAdd(&proxy[1], e1/s);
        atomicAdd(&proxy[2], e2/s);
    }
    __syncthreads();
    if (t == 0 && out_size > N_OUT) {
        float aux = 0.f;
        for (int e = 0; e < NEXP; e++)
            aux += ((float)cnt[e] / (float)B) * (proxy[e] / (float)B);
        out[N_OUT] = 0.01f * (aux * (float)NEXP);
    }
}

// =====================================================================
// Kernel 5: FUSED head conv1 3x3 (64->384) + grouped 1x1 (->2 ch per ocb) + out
// (R14 verified)
// =====================================================================
__global__ void __launch_bounds__(256)
head_fused_mma(const float* __restrict__ hb1,
               const float* __restrict__ hw2,
               const float* __restrict__ hb2,
               float* __restrict__ out)
{
    extern __shared__ char smem[];
    __shared__ float w0s[128], w1s[128], b1s[128];
    __shared__ float red0[256], red1[256];
    const uint32_t sb = smem_u32(smem);
    const int tid = threadIdx.x;
    const int wid = tid >> 5, lid = tid & 31;
    const int b   = blockIdx.z;
    const int ocb = blockIdx.y;
    const int p0  = blockIdx.x * 128;
    const int e   = g_idx[b];

    if (tid < 128) {
        w0s[tid] = hw2[(e*6 + 2*ocb)*128 + tid];
        b1s[tid] = hb1[e*384 + ocb*128 + tid];
    } else {
        w1s[tid - 128] = hw2[(e*6 + 2*ocb + 1)*128 + (tid - 128)];
    }

    const int warpM = wid >> 2, warpN = wid & 3;
    const int m0w = warpM * 64, n0w = warpN * 32;

    float acc[4][4][4];
    #pragma unroll
    for (int mt = 0; mt < 4; mt++)
        #pragma unroll
        for (int nt = 0; nt < 4; nt++)
            #pragma unroll
            for (int q = 0; q < 4; q++) acc[mt][nt][q] = 0.f;

    const int n = tid & 127;
    const int g = tid >> 7;
    const int p = p0 + n;
    const int pr = p / 96;
    const int pc = p - pr*96;
    const uint32_t* y1b = g_y1p + (size_t)b * 64 * PH*PH;

    const int rr  = lid & 7;
    const int sel = lid >> 3;

    for (int tap = 0; tap < 9; tap++) {
        const int kh = tap / 3, kw = tap - 3*(tap/3);
        __syncthreads();

        {
            const __nv_bfloat16* whb = g_wh + ((size_t)((e*9 + tap)*384 + ocb*128))*64;
            const __nv_bfloat16* wlb = g_wl + ((size_t)((e*9 + tap)*384 + ocb*128))*64;
            #pragma unroll
            for (int it = 0; it < 8; it++) {
                int idx = it*256 + tid;
                int s   = idx >> 10;
                int r   = idx & 1023;
                int oc  = r >> 3;
                int ch  = r & 7;
                const __nv_bfloat16* src = (s ? wlb : whb) + oc*64 + ch*8;
                uint4 v = *(const uint4*)src;
                *(uint4*)(smem + s*16384 + SW128((uint32_t)(oc*128 + ch*16))) = v;
            }
        }

        {
            const int ri = pr + kh - 1, ci = pc + kw - 1;
            const bool ok = ((unsigned)ri < 96u) && ((unsigned)ci < 96u);
            const uint32_t* yq = y1b + (size_t)ri*96 + ci;
            #pragma unroll
            for (int j = 0; j < 4; j++) {
                const int ic0 = g*32 + j*8;
                uint32_t pv[8];
                #pragma unroll
                for (int u = 0; u < 8; u++)
                    pv[u] = ok ? __ldg(yq + (size_t)(ic0 + u) * (PH*PH)) : 0u;
                uint32_t hp[4], lp[4];
                #pragma unroll
                for (int u = 0; u < 4; u++) {
                    hp[u] = __byte_perm(pv[2*u], pv[2*u+1], 0x5410);
                    lp[u] = __byte_perm(pv[2*u], pv[2*u+1], 0x7632);
                }
                const uint32_t off = SW128((uint32_t)(n*128 + ic0*2));
                *(uint4*)(smem + 32768 + off) = make_uint4(hp[0], hp[1], hp[2], hp[3]);
                *(uint4*)(smem + 49152 + off) = make_uint4(lp[0], lp[1], lp[2], lp[3]);
            }
        }
        __syncthreads();

        #pragma unroll
        for (int kc = 0; kc < 4; kc++) {
            const int k0b = kc*32;

            uint32_t ah[4][4], al[4][4];
            {
                const int arow = m0w + (sel & 1)*8 + rr;
                const int akb  = k0b + ((sel >> 1)*8)*2;
                #pragma unroll
                for (int mt = 0; mt < 4; mt++) {
                    uint32_t off = SW128((uint32_t)((arow + mt*16)*128 + akb));
                    LDSM4(ah[mt][0], ah[mt][1], ah[mt][2], ah[mt][3], sb + off);
                    LDSM4(al[mt][0], al[mt][1], al[mt][2], al[mt][3], sb + 16384 + off);
                }
            }

            uint32_t bh[4][2], bl[4][2];
            {
                const int brow = n0w + (sel >> 1)*8 + rr;
                const int bkb  = k0b + ((sel & 1)*8)*2;
                #pragma unroll
                for (int pair = 0; pair < 2; pair++) {
                    uint32_t off = SW128((uint32_t)((brow + pair*16)*128 + bkb));
                    LDSM4(bh[pair*2][0], bh[pair*2][1], bh[pair*2+1][0], bh[pair*2+1][1],
                          sb + 32768 + off);
                    LDSM4(bl[pair*2][0], bl[pair*2][1], bl[pair*2+1][0], bl[pair*2+1][1],
                          sb + 49152 + off);
                }
            }

            #pragma unroll
            for (int mt = 0; mt < 4; mt++)
                #pragma unroll
                for (int nt = 0; nt < 4; nt++) {
                    MMA16816(acc[mt][nt], ah[mt], bh[nt][0], bh[nt][1]);
                    MMA16816(acc[mt][nt], ah[mt], bl[nt][0], bl[nt][1]);
                    MMA16816(acc[mt][nt], al[mt], bh[nt][0], bh[nt][1]);
                }
        }
    }

    // ---- fused epilogue: acc -> epi smem [128 oc][128 px], then 1x1 conv -> out
    __syncthreads();
    float* epi = (float*)smem;
    {
        const int r  = lid >> 2;
        const int cc = (lid & 3) * 2;
        #pragma unroll
        for (int mt = 0; mt < 4; mt++)
            #pragma unroll
            for (int nt = 0; nt < 4; nt++) {
                const int m  = m0w + mt*16 + r;
                const int nn = n0w + nt*8 + cc;
                epi[m*128 + nn]         = acc[mt][nt][0];
                epi[m*128 + nn + 1]     = acc[mt][nt][1];
                epi[(m+8)*128 + nn]     = acc[mt][nt][2];
                epi[(m+8)*128 + nn + 1] = acc[mt][nt][3];
            }
    }
    __syncthreads();
    {
        const int px = tid & 127;
        const int h  = tid >> 7;
        float s0 = 0.f, s1 = 0.f;
        #pragma unroll 8
        for (int j = 0; j < 64; j++) {
            const int oc = h*64 + j;
            float v = fmaxf(epi[oc*128 + px] + b1s[oc], 0.f);
            s0 += v * w0s[oc];
            s1 += v * w1s[oc];
        }
        red0[tid] = s0;
        red1[tid] = s1;
    }
    __syncthreads();
    if (tid < 128) {
        const int px = tid;
        float o0 = hb2[e*6 + 2*ocb]     + red0[px] + red0[128 + px];
        float o1 = hb2[e*6 + 2*ocb + 1] + red1[px] + red1[128 + px];
        out[((size_t)(b*6 + 2*ocb))    *(PH*PH) + p0 + px] = o0;
        out[((size_t)(b*6 + 2*ocb + 1))*(PH*PH) + p0 + px] = o1;
    }
}

// =====================================================================
// launcher
// =====================================================================
extern "C" void kernel_launch(void* const* d_in, const int* in_sizes, int n_in,
                              void* d_out, int out_size)
{
    const float* x        = (const float*)d_in[0];
    const float* g_conv_w = (const float*)d_in[1];
    const float* g_gamma  = (const float*)d_in[2];
    const float* g_beta   = (const float*)d_in[3];
    const float* g_mean   = (const float*)d_in[4];
    const float* g_var    = (const float*)d_in[5];
    const float* g_fc_w   = (const float*)d_in[6];
    const float* g_fc_b   = (const float*)d_in[7];
    const float* e_conv1_w = (const float*)d_in[8];
    const float* e_conv1_b = (const float*)d_in[9];
    const float* e_head_w1 = (const float*)d_in[10];
    const float* e_head_b1 = (const float*)d_in[11];
    const float* e_head_w2 = (const float*)d_in[12];
    const float* e_head_b2 = (const float*)d_in[13];
    float* out = (float*)d_out;

    cudaFuncSetAttribute(head_fused_mma,
                         cudaFuncAttributeMaxDynamicSharedMemorySize, 65536);
    cudaFuncSetAttribute(gating_mma,
                         cudaFuncAttributeMaxDynamicSharedMemorySize, 32768);
    cudaFuncSetAttribute(expert_mma,
                         cudaFuncAttributeMaxDynamicSharedMemorySize, 32768);

    gw_convert<<<(49*64*16 + 255)/256, 256>>>(g_conv_w);
    ew_convert<<<(NEXP*49*64*16 + 255)/256, 256>>>(e_conv1_w);
    w_convert<<<(NEXP*384*64*9 + 255)/256, 256>>>(e_head_w1);

    size_t nx = (size_t)B*CIN*HIN*HIN;
    xf_convert<<<(unsigned)((nx/4 + 255)/256), 256>>>(x);

    dim3 ggate(GH*GH/256, B);                    // 144, 16
    gating_mma<<<ggate, 256, 32768>>>(g_gamma, g_beta, g_mean, g_var);

    pool_mean<<<B*64, 256>>>();

    gate_head<<<1, 64>>>(g_fc_w, g_fc_b, out, out_size);

    dim3 gexp(PH*PH/256, B);                     // 36, 16
    expert_mma<<<gexp, 256, 32768>>>(e_conv1_b);

    dim3 ghead(PH*PH/128, 3, B);                 // 72, 3, 16
    head_fused_mma<<<ghead, 256, 65536>>>(e_head_b1, e_head_w2, e_head_b2, out);
}